// round 6
// baseline (speedup 1.0000x reference)
#include <cuda_runtime.h>
#include <cuda_bf16.h>
#include <cstdint>

#define S_LEN 4096
#define D_MODEL 768
#define NHEAD 12
#define WHEAD 64
#define N_QKV 2304

// ---------------- scratch: tf32 bit patterns, k-permuted layouts ----------------
// Pmap(x) permutes the 0..63 index so MMA fragments are LDS.128-contiguous.
__device__ float g_q[NHEAD * S_LEN * WHEAD];    // [h][s][Pmap(w)]
__device__ float g_k[NHEAD * S_LEN * WHEAD];    // [h][s][Pmap(w)]
__device__ float g_v[NHEAD * WHEAD * S_LEN];    // [h][w][blk64(s)|Pmap(s%64)]

// ---------------- helpers ----------------
__device__ __forceinline__ uint32_t f2tf32(float x) {
    uint32_t u;
    asm("cvt.rna.tf32.f32 %0, %1;" : "=r"(u) : "f"(x));
    return u;
}
__device__ __forceinline__ float ex2(float x) {
    float y;
    asm("ex2.approx.f32 %0, %1;" : "=f"(y) : "f"(x));
    return y;
}
__device__ __forceinline__ int pmap(int x) {   // [b5 b4 b1 b0 b3 b2]
    return (x & 48) | ((x & 3) << 2) | ((x >> 2) & 2) | ((x >> 2) & 1);
}

__device__ __forceinline__ void mma_tf32(
    float& d0, float& d1, float& d2, float& d3,
    uint32_t a0, uint32_t a1, uint32_t a2, uint32_t a3,
    uint32_t b0, uint32_t b1)
{
    asm volatile(
        "mma.sync.aligned.m16n8k8.row.col.f32.tf32.tf32.f32 "
        "{%0,%1,%2,%3},{%4,%5,%6,%7},{%8,%9},{%0,%1,%2,%3};"
        : "+f"(d0), "+f"(d1), "+f"(d2), "+f"(d3)
        : "r"(a0), "r"(a1), "r"(a2), "r"(a3), "r"(b0), "r"(b1));
}

__device__ __forceinline__ void cpa16(void* s, const void* g) {
    uint32_t sa = (uint32_t)__cvta_generic_to_shared(s);
    asm volatile("cp.async.cg.shared.global [%0], [%1], 16;" :: "r"(sa), "l"(g));
}
#define CPA_COMMIT() asm volatile("cp.async.commit_group;" ::: "memory")
#define CPA_WAIT0()  asm volatile("cp.async.wait_group 0;" ::: "memory")

// =============== Kernel 1: QKV GEMM (tf32, cp.async double-buffered) ===============
#define GAP 36
#define GBP 72

__global__ __launch_bounds__(256) void qkv_gemm_tc(
    const float* __restrict__ X, const float* __restrict__ Wq,
    const float* __restrict__ bq)
{
    __shared__ float As[2][128 * GAP];
    __shared__ float Bs[2][32 * GBP];

    const int tid = threadIdx.x;
    const int wid = tid >> 5;
    const int lane = tid & 31;
    const int g = lane >> 2;
    const int c = lane & 3;
    const int warp_m = wid >> 1;
    const int warp_n = wid & 1;
    const int m0 = blockIdx.y * 128;
    const int n0 = blockIdx.x * 64;

    float acc[2][4][4];
#pragma unroll
    for (int mt = 0; mt < 2; ++mt)
#pragma unroll
        for (int nt = 0; nt < 4; ++nt)
#pragma unroll
            for (int i = 0; i < 4; ++i) acc[mt][nt][i] = 0.0f;

    const int rowA = tid >> 3, c4A = tid & 7;
    const int rowB = tid >> 4, c4B = tid & 15;

    auto issue = [&](int k0, int buf) {
#pragma unroll
        for (int r = 0; r < 4; ++r) {
            int row = rowA + r * 32;
            cpa16(&As[buf][row * GAP + c4A * 4],
                  &X[(size_t)(m0 + row) * D_MODEL + k0 + c4A * 4]);
        }
#pragma unroll
        for (int r = 0; r < 2; ++r) {
            int row = rowB + r * 16;
            cpa16(&Bs[buf][row * GBP + c4B * 4],
                  &Wq[(size_t)(k0 + row) * N_QKV + n0 + c4B * 4]);
        }
        CPA_COMMIT();
    };

    issue(0, 0);
    for (int i = 0; i < 24; ++i) {
        CPA_WAIT0();
        __syncthreads();
        if (i + 1 < 24) issue((i + 1) * 32, (i + 1) & 1);
        const float* A = As[i & 1];
        const float* B = Bs[i & 1];
#pragma unroll
        for (int kk = 0; kk < 4; ++kk) {
            uint32_t af[2][4];
#pragma unroll
            for (int mt = 0; mt < 2; ++mt) {
                int mr = warp_m * 32 + mt * 16 + g;
                af[mt][0] = f2tf32(A[mr * GAP + kk * 8 + c]);
                af[mt][1] = f2tf32(A[(mr + 8) * GAP + kk * 8 + c]);
                af[mt][2] = f2tf32(A[mr * GAP + kk * 8 + c + 4]);
                af[mt][3] = f2tf32(A[(mr + 8) * GAP + kk * 8 + c + 4]);
            }
#pragma unroll
            for (int nt = 0; nt < 4; ++nt) {
                int nc = warp_n * 32 + nt * 8 + g;
                uint32_t b0 = f2tf32(B[(kk * 8 + c) * GBP + nc]);
                uint32_t b1 = f2tf32(B[(kk * 8 + c + 4) * GBP + nc]);
#pragma unroll
                for (int mt = 0; mt < 2; ++mt)
                    mma_tf32(acc[mt][nt][0], acc[mt][nt][1], acc[mt][nt][2], acc[mt][nt][3],
                             af[mt][0], af[mt][1], af[mt][2], af[mt][3], b0, b1);
            }
        }
        __syncthreads();
    }

    // epilogue: bias, tf32-convert, permuted scatter
    const int sel = n0 / D_MODEL;
    const int head = (n0 % D_MODEL) / WHEAD;

#pragma unroll
    for (int mt = 0; mt < 2; ++mt) {
#pragma unroll
        for (int nt = 0; nt < 4; ++nt) {
            int w = warp_n * 32 + nt * 8 + 2 * c;
            float b0 = bq[n0 + w], b1 = bq[n0 + w + 1];
            int m_lo = m0 + warp_m * 32 + mt * 16 + g;
            float v00 = __uint_as_float(f2tf32(acc[mt][nt][0] + b0));
            float v01 = __uint_as_float(f2tf32(acc[mt][nt][1] + b1));
            float v10 = __uint_as_float(f2tf32(acc[mt][nt][2] + b0));
            float v11 = __uint_as_float(f2tf32(acc[mt][nt][3] + b1));
            if (sel == 2) {   // V: [h][w][perm(s)]
                float* vt = g_v + (size_t)head * WHEAD * S_LEN;
                int s0p = (m_lo & ~63) | pmap(m_lo & 63);
                int s1p = ((m_lo + 8) & ~63) | pmap((m_lo + 8) & 63);
                vt[(size_t)w * S_LEN + s0p] = v00;
                vt[(size_t)(w + 1) * S_LEN + s0p] = v01;
                vt[(size_t)w * S_LEN + s1p] = v10;
                vt[(size_t)(w + 1) * S_LEN + s1p] = v11;
            } else {          // Q/K: [h][s][pmap(w)]
                float* dst = (sel == 0) ? g_q : g_k;
                int w0p = pmap(w), w1p = pmap(w + 1);
                dst[((size_t)head * S_LEN + m_lo) * WHEAD + w0p] = v00;
                dst[((size_t)head * S_LEN + m_lo) * WHEAD + w1p] = v01;
                dst[((size_t)head * S_LEN + m_lo + 8) * WHEAD + w0p] = v10;
                dst[((size_t)head * S_LEN + m_lo + 8) * WHEAD + w1p] = v11;
            }
        }
    }
}

// =============== Kernel 2: flash attention (tf32, LDS.128 fragments) ===============
// smem (floats): Q 128x64, K 64x64, V 64x64, mask 2x64. XOR-16 swizzle by row parity.
#define SM_Q   0
#define SM_K   (128 * 64)
#define SM_V   (SM_K + 64 * 64)
#define SM_AM  (SM_V + 64 * 64)
#define ATTN_SMEM_F (SM_AM + 2 * 64)
#define ATTN_SMEM_BYTES (ATTN_SMEM_F * 4)   // 66048 B -> 3 CTAs/SM

#define LOG2E 1.4426950408889634f
#define SCL   (0.125f * LOG2E)
#define AMC   (10000.0f * LOG2E)

__global__ __launch_bounds__(128, 3) void attn_tc(
    const float* __restrict__ mask, float* __restrict__ out)
{
    extern __shared__ float smf[];

    const int tid = threadIdx.x;
    const int wid = tid >> 5;
    const int lane = tid & 31;
    const int g = lane >> 2;
    const int c = lane & 3;
    const int srcA = (lane & 28) | (c >> 1);
    const int srcB = srcA + 2;
    const int r0 = blockIdx.x * 128;
    const int head = blockIdx.y;

    const float* qh = g_q + (size_t)head * S_LEN * WHEAD;
    const float* kh = g_k + (size_t)head * S_LEN * WHEAD;
    const float* vt = g_v + (size_t)head * WHEAD * S_LEN;

    const int rowL = tid >> 4;           // 0..7 (+8r)
    const int c4L = tid & 15;            // 16B chunk in a 64-float row

    // swizzled chunk col for (row, chunk)
    auto scol = [&](int row, int c4) { return ((c4 ^ ((row & 1) << 2)) * 4); };

    // ---- prologue: Q(128x64), K(0), V(0), mask(0) ----
#pragma unroll
    for (int r = 0; r < 16; ++r) {
        int row = rowL + r * 8;
        cpa16(&smf[SM_Q + row * 64 + scol(row, c4L)],
              &qh[(size_t)(r0 + row) * WHEAD + c4L * 4]);
    }
#pragma unroll
    for (int r = 0; r < 8; ++r) {
        int row = rowL + r * 8;
        cpa16(&smf[SM_K + row * 64 + scol(row, c4L)],
              &kh[(size_t)row * WHEAD + c4L * 4]);
        cpa16(&smf[SM_V + row * 64 + scol(row, c4L)],
              &vt[(size_t)row * S_LEN + c4L * 4]);
    }
    if (tid < 16) cpa16(&smf[SM_AM + tid * 4], &mask[tid * 4]);
    CPA_COMMIT();

    float oacc[2][8][4];
#pragma unroll
    for (int mt = 0; mt < 2; ++mt)
#pragma unroll
        for (int nt = 0; nt < 8; ++nt)
#pragma unroll
            for (int i = 0; i < 4; ++i) oacc[mt][nt][i] = 0.0f;
    float mrow[2][2], lrow[2][2];
#pragma unroll
    for (int mt = 0; mt < 2; ++mt) {
        mrow[mt][0] = mrow[mt][1] = -1e30f;
        lrow[mt][0] = lrow[mt][1] = 0.0f;
    }

    CPA_WAIT0();
    __syncthreads();

    for (int t = 0; t < S_LEN / 64; ++t) {
        // ---- S = Q K^T ----
        float sacc[2][8][4];
#pragma unroll
        for (int mt = 0; mt < 2; ++mt)
#pragma unroll
            for (int nt = 0; nt < 8; ++nt)
#pragma unroll
                for (int i = 0; i < 4; ++i) sacc[mt][nt][i] = 0.0f;

#pragma unroll
        for (int p = 0; p < 4; ++p) {
            const int cb = p * 16 + c * 4;
            float4 qa[2][2];
#pragma unroll
            for (int mt = 0; mt < 2; ++mt) {
                int mr = wid * 32 + mt * 16 + g;
                qa[mt][0] = *(const float4*)&smf[SM_Q + mr * 64 + (cb ^ ((mr & 1) << 4))];
                qa[mt][1] = *(const float4*)&smf[SM_Q + (mr + 8) * 64 + (cb ^ ((mr & 1) << 4))];
            }
#pragma unroll
            for (int nt = 0; nt < 8; ++nt) {
                int kr = nt * 8 + g;
                float4 kb = *(const float4*)&smf[SM_K + kr * 64 + (cb ^ ((kr & 1) << 4))];
#pragma unroll
                for (int mt = 0; mt < 2; ++mt) {
                    mma_tf32(sacc[mt][nt][0], sacc[mt][nt][1], sacc[mt][nt][2], sacc[mt][nt][3],
                             __float_as_uint(qa[mt][0].x), __float_as_uint(qa[mt][1].x),
                             __float_as_uint(qa[mt][0].y), __float_as_uint(qa[mt][1].y),
                             __float_as_uint(kb.x), __float_as_uint(kb.y));
                    mma_tf32(sacc[mt][nt][0], sacc[mt][nt][1], sacc[mt][nt][2], sacc[mt][nt][3],
                             __float_as_uint(qa[mt][0].z), __float_as_uint(qa[mt][1].z),
                             __float_as_uint(qa[mt][0].w), __float_as_uint(qa[mt][1].w),
                             __float_as_uint(kb.z), __float_as_uint(kb.w));
                }
            }
        }

        __syncthreads();   // all warps done reading K
        // ---- prefetch K(t+1) + mask(t+1) (overlaps softmax + PV) ----
        if (t + 1 < S_LEN / 64) {
            const int t1 = (t + 1) * 64;
#pragma unroll
            for (int r = 0; r < 8; ++r) {
                int row = rowL + r * 8;
                cpa16(&smf[SM_K + row * 64 + scol(row, c4L)],
                      &kh[(size_t)(t1 + row) * WHEAD + c4L * 4]);
            }
            if (tid < 16) cpa16(&smf[SM_AM + ((t + 1) & 1) * 64 + tid * 4], &mask[t1 + tid * 4]);
        }
        CPA_COMMIT();

        // ---- additive mask (log2 domain); S cols are natural j ----
        float amv[8][2];
#pragma unroll
        for (int nt = 0; nt < 8; ++nt) {
            float m0v = smf[SM_AM + (t & 1) * 64 + nt * 8 + 2 * c];
            float m1v = smf[SM_AM + (t & 1) * 64 + nt * 8 + 2 * c + 1];
            amv[nt][0] = fmaf(m0v, AMC, -AMC);
            amv[nt][1] = fmaf(m1v, AMC, -AMC);
        }

        // ---- online softmax per m-tile ----
#pragma unroll
        for (int mt = 0; mt < 2; ++mt) {
            float vmax_lo = -1e30f, vmax_hi = -1e30f;
#pragma unroll
            for (int nt = 0; nt < 8; ++nt) {
                sacc[mt][nt][0] = fmaf(sacc[mt][nt][0], SCL, amv[nt][0]);
                sacc[mt][nt][1] = fmaf(sacc[mt][nt][1], SCL, amv[nt][1]);
                sacc[mt][nt][2] = fmaf(sacc[mt][nt][2], SCL, amv[nt][0]);
                sacc[mt][nt][3] = fmaf(sacc[mt][nt][3], SCL, amv[nt][1]);
                vmax_lo = fmaxf(vmax_lo, fmaxf(sacc[mt][nt][0], sacc[mt][nt][1]));
                vmax_hi = fmaxf(vmax_hi, fmaxf(sacc[mt][nt][2], sacc[mt][nt][3]));
            }
#pragma unroll
            for (int off = 1; off <= 2; off <<= 1) {
                vmax_lo = fmaxf(vmax_lo, __shfl_xor_sync(0xffffffffu, vmax_lo, off));
                vmax_hi = fmaxf(vmax_hi, __shfl_xor_sync(0xffffffffu, vmax_hi, off));
            }
            float mn_lo = fmaxf(mrow[mt][0], vmax_lo);
            float mn_hi = fmaxf(mrow[mt][1], vmax_hi);
            float corr_lo = ex2(mrow[mt][0] - mn_lo);
            float corr_hi = ex2(mrow[mt][1] - mn_hi);
            float rs_lo = 0.0f, rs_hi = 0.0f;
#pragma unroll
            for (int nt = 0; nt < 8; ++nt) {
                sacc[mt][nt][0] = ex2(sacc[mt][nt][0] - mn_lo);
                sacc[mt][nt][1] = ex2(sacc[mt][nt][1] - mn_lo);
                sacc[mt][nt][2] = ex2(sacc[mt][nt][2] - mn_hi);
                sacc[mt][nt][3] = ex2(sacc[mt][nt][3] - mn_hi);
                rs_lo += sacc[mt][nt][0] + sacc[mt][nt][1];
                rs_hi += sacc[mt][nt][2] + sacc[mt][nt][3];
            }
#pragma unroll
            for (int off = 1; off <= 2; off <<= 1) {
                rs_lo += __shfl_xor_sync(0xffffffffu, rs_lo, off);
                rs_hi += __shfl_xor_sync(0xffffffffu, rs_hi, off);
            }
            lrow[mt][0] = lrow[mt][0] * corr_lo + rs_lo;
            lrow[mt][1] = lrow[mt][1] * corr_hi + rs_hi;
            mrow[mt][0] = mn_lo; mrow[mt][1] = mn_hi;
#pragma unroll
            for (int nt = 0; nt < 8; ++nt) {
                oacc[mt][nt][0] *= corr_lo; oacc[mt][nt][1] *= corr_lo;
                oacc[mt][nt][2] *= corr_hi; oacc[mt][nt][3] *= corr_hi;
            }
        }

        // ---- P -> tf32 bits in place ----
#pragma unroll
        for (int mt = 0; mt < 2; ++mt)
#pragma unroll
            for (int nt = 0; nt < 8; ++nt)
#pragma unroll
                for (int i = 0; i < 4; ++i)
                    sacc[mt][nt][i] = __uint_as_float(f2tf32(sacc[mt][nt][i]));

        // ---- O += P V ; A-frags via intra-quad shuffles, V B-frags LDS.128 ----
#pragma unroll
        for (int p = 0; p < 4; ++p) {
            const int cb = p * 16 + c * 4;
            uint32_t af[2][2][4];   // [kk parity][mt][4]
#pragma unroll
            for (int half = 0; half < 2; ++half) {
                int kk = 2 * p + half;
#pragma unroll
                for (int mt = 0; mt < 2; ++mt) {
                    uint32_t p0 = __float_as_uint(sacc[mt][kk][0]);
                    uint32_t p1 = __float_as_uint(sacc[mt][kk][1]);
                    uint32_t p2 = __float_as_uint(sacc[mt][kk][2]);
                    uint32_t p3 = __float_as_uint(sacc[mt][kk][3]);
                    uint32_t x0 = __shfl_sync(0xffffffffu, p0, srcA);
                    uint32_t x1 = __shfl_sync(0xffffffffu, p1, srcA);
                    uint32_t y0 = __shfl_sync(0xffffffffu, p0, srcB);
                    uint32_t y1 = __shfl_sync(0xffffffffu, p1, srcB);
                    af[half][mt][0] = (c & 1) ? x1 : x0;
                    af[half][mt][2] = (c & 1) ? y1 : y0;
                    uint32_t x2 = __shfl_sync(0xffffffffu, p2, srcA);
                    uint32_t x3 = __shfl_sync(0xffffffffu, p3, srcA);
                    uint32_t y2 = __shfl_sync(0xffffffffu, p2, srcB);
                    uint32_t y3 = __shfl_sync(0xffffffffu, p3, srcB);
                    af[half][mt][1] = (c & 1) ? x3 : x2;
                    af[half][mt][3] = (c & 1) ? y3 : y2;
                }
            }
#pragma unroll
            for (int nt = 0; nt < 8; ++nt) {
                int vr = nt * 8 + g;
                float4 vb = *(const float4*)&smf[SM_V + vr * 64 + (cb ^ ((vr & 1) << 4))];
#pragma unroll
                for (int mt = 0; mt < 2; ++mt) {
                    mma_tf32(oacc[mt][nt][0], oacc[mt][nt][1], oacc[mt][nt][2], oacc[mt][nt][3],
                             af[0][mt][0], af[0][mt][1], af[0][mt][2], af[0][mt][3],
                             __float_as_uint(vb.x), __float_as_uint(vb.y));
                    mma_tf32(oacc[mt][nt][0], oacc[mt][nt][1], oacc[mt][nt][2], oacc[mt][nt][3],
                             af[1][mt][0], af[1][mt][1], af[1][mt][2], af[1][mt][3],
                             __float_as_uint(vb.z), __float_as_uint(vb.w));
                }
            }
        }

        __syncthreads();   // all warps done reading V
        // ---- prefetch V(t+1) ----
        if (t + 1 < S_LEN / 64) {
            const int t1 = (t + 1) * 64;
#pragma unroll
            for (int r = 0; r < 8; ++r) {
                int row = rowL + r * 8;
                cpa16(&smf[SM_V + row * 64 + scol(row, c4L)],
                      &vt[(size_t)row * S_LEN + t1 + c4L * 4]);
            }
        }
        CPA_COMMIT();
        CPA_WAIT0();
        __syncthreads();
    }

    // ---- epilogue (output cols are natural w) ----
#pragma unroll
    for (int mt = 0; mt < 2; ++mt) {
        float inv_lo = 1.0f / lrow[mt][0];
        float inv_hi = 1.0f / lrow[mt][1];
        int row_lo = r0 + wid * 32 + mt * 16 + g;
#pragma unroll
        for (int nt = 0; nt < 8; ++nt) {
            int col = head * WHEAD + nt * 8 + 2 * c;
            float2 lo = make_float2(oacc[mt][nt][0] * inv_lo, oacc[mt][nt][1] * inv_lo);
            float2 hi = make_float2(oacc[mt][nt][2] * inv_hi, oacc[mt][nt][3] * inv_hi);
            *(float2*)&out[(size_t)row_lo * D_MODEL + col] = lo;
            *(float2*)&out[(size_t)(row_lo + 8) * D_MODEL + col] = hi;
        }
    }
}

// ---------------- launch ----------------
extern "C" void kernel_launch(void* const* d_in, const int* in_sizes, int n_in,
                              void* d_out, int out_size)
{
    const float* x    = (const float*)d_in[0];
    const float* mask = (const float*)d_in[1];
    const float* Wq   = (const float*)d_in[2];
    const float* bq   = (const float*)d_in[3];
    float* out = (float*)d_out;

    dim3 gGemm(N_QKV / 64, S_LEN / 128);         // (36, 32)
    qkv_gemm_tc<<<gGemm, 256>>>(x, Wq, bq);

    cudaFuncSetAttribute(attn_tc,
                         cudaFuncAttributeMaxDynamicSharedMemorySize,
                         ATTN_SMEM_BYTES);
    dim3 gAttn(S_LEN / 128, NHEAD);              // (32, 12)
    attn_tc<<<gAttn, 128, ATTN_SMEM_BYTES>>>(mask, out);
}

// round 7
// speedup vs baseline: 1.5377x; 1.5377x over previous
#include <cuda_runtime.h>
#include <cuda_bf16.h>
#include <cstdint>

#define S_LEN 4096
#define D_MODEL 768
#define NHEAD 12
#define WHEAD 64
#define N_QKV 2304

// ---------------- scratch: tf32 bit patterns, k-permuted layouts ----------------
__device__ float g_q[NHEAD * S_LEN * WHEAD];    // [h][s][pmap(w)]
__device__ float g_k[NHEAD * S_LEN * WHEAD];    // [h][s][pmap(w)]
__device__ float g_v[NHEAD * WHEAD * S_LEN];    // [h][w][blk64(s)|pmap(s%64)]

// ---------------- helpers ----------------
__device__ __forceinline__ uint32_t f2tf32(float x) {
    uint32_t u;
    asm("cvt.rna.tf32.f32 %0, %1;" : "=r"(u) : "f"(x));
    return u;
}
__device__ __forceinline__ float ex2(float x) {
    float y;
    asm("ex2.approx.f32 %0, %1;" : "=f"(y) : "f"(x));
    return y;
}
__device__ __forceinline__ int pmap(int x) {   // [b5 b4 b1 b0 b3 b2]; involution
    return (x & 48) | ((x & 3) << 2) | ((x >> 2) & 3);
}
// conflict-free chunk swizzle: float col of 16B chunk c4 in row
__device__ __forceinline__ int swz(int row, int c4) {
    return (c4 ^ ((row & 3) << 2)) * 4;
}

__device__ __forceinline__ void mma_tf32(
    float& d0, float& d1, float& d2, float& d3,
    uint32_t a0, uint32_t a1, uint32_t a2, uint32_t a3,
    uint32_t b0, uint32_t b1)
{
    asm volatile(
        "mma.sync.aligned.m16n8k8.row.col.f32.tf32.tf32.f32 "
        "{%0,%1,%2,%3},{%4,%5,%6,%7},{%8,%9},{%0,%1,%2,%3};"
        : "+f"(d0), "+f"(d1), "+f"(d2), "+f"(d3)
        : "r"(a0), "r"(a1), "r"(a2), "r"(a3), "r"(b0), "r"(b1));
}

__device__ __forceinline__ void cpa16(void* s, const void* g) {
    uint32_t sa = (uint32_t)__cvta_generic_to_shared(s);
    asm volatile("cp.async.cg.shared.global [%0], [%1], 16;" :: "r"(sa), "l"(g));
}
#define CPA_COMMIT() asm volatile("cp.async.commit_group;" ::: "memory")
#define CPA_WAIT0()  asm volatile("cp.async.wait_group 0;" ::: "memory")

// =============== Kernel 1: QKV GEMM (tf32, cp.async double-buffered) ===============
#define GAP 36
#define GBP 72
#define CTP 66   // epilogue staging pitch

__global__ __launch_bounds__(256) void qkv_gemm_tc(
    const float* __restrict__ X, const float* __restrict__ Wq,
    const float* __restrict__ bq)
{
    __shared__ float As[2][128 * GAP];   // also reused as 128xCTP staging tile
    __shared__ float Bs[2][32 * GBP];

    const int tid = threadIdx.x;
    const int wid = tid >> 5;
    const int lane = tid & 31;
    const int g = lane >> 2;
    const int c = lane & 3;
    const int warp_m = wid >> 1;
    const int warp_n = wid & 1;
    const int m0 = blockIdx.y * 128;
    const int n0 = blockIdx.x * 64;

    float acc[2][4][4];
#pragma unroll
    for (int mt = 0; mt < 2; ++mt)
#pragma unroll
        for (int nt = 0; nt < 4; ++nt)
#pragma unroll
            for (int i = 0; i < 4; ++i) acc[mt][nt][i] = 0.0f;

    const int rowA = tid >> 3, c4A = tid & 7;
    const int rowB = tid >> 4, c4B = tid & 15;

    auto issue = [&](int k0, int buf) {
#pragma unroll
        for (int r = 0; r < 4; ++r) {
            int row = rowA + r * 32;
            cpa16(&As[buf][row * GAP + c4A * 4],
                  &X[(size_t)(m0 + row) * D_MODEL + k0 + c4A * 4]);
        }
#pragma unroll
        for (int r = 0; r < 2; ++r) {
            int row = rowB + r * 16;
            cpa16(&Bs[buf][row * GBP + c4B * 4],
                  &Wq[(size_t)(k0 + row) * N_QKV + n0 + c4B * 4]);
        }
        CPA_COMMIT();
    };

    issue(0, 0);
    for (int i = 0; i < 24; ++i) {
        CPA_WAIT0();
        __syncthreads();
        if (i + 1 < 24) issue((i + 1) * 32, (i + 1) & 1);
        const float* A = As[i & 1];
        const float* B = Bs[i & 1];
#pragma unroll
        for (int kk = 0; kk < 4; ++kk) {
            uint32_t af[2][4];
#pragma unroll
            for (int mt = 0; mt < 2; ++mt) {
                int mr = warp_m * 32 + mt * 16 + g;
                af[mt][0] = f2tf32(A[mr * GAP + kk * 8 + c]);
                af[mt][1] = f2tf32(A[(mr + 8) * GAP + kk * 8 + c]);
                af[mt][2] = f2tf32(A[mr * GAP + kk * 8 + c + 4]);
                af[mt][3] = f2tf32(A[(mr + 8) * GAP + kk * 8 + c + 4]);
            }
#pragma unroll
            for (int nt = 0; nt < 4; ++nt) {
                int nc = warp_n * 32 + nt * 8 + g;
                uint32_t b0 = f2tf32(B[(kk * 8 + c) * GBP + nc]);
                uint32_t b1 = f2tf32(B[(kk * 8 + c + 4) * GBP + nc]);
#pragma unroll
                for (int mt = 0; mt < 2; ++mt)
                    mma_tf32(acc[mt][nt][0], acc[mt][nt][1], acc[mt][nt][2], acc[mt][nt][3],
                             af[mt][0], af[mt][1], af[mt][2], af[mt][3], b0, b1);
            }
        }
        __syncthreads();
    }

    // ---- epilogue: bias + tf32, stage C-tile in smem, coalesced permuted writes ----
    const int sel = n0 / D_MODEL;
    const int head = (n0 % D_MODEL) / WHEAD;
    float* Ct = &As[0][0];   // 128 x CTP staging (33 KB <= 36 KB)

#pragma unroll
    for (int mt = 0; mt < 2; ++mt) {
#pragma unroll
        for (int nt = 0; nt < 4; ++nt) {
            int w = warp_n * 32 + nt * 8 + 2 * c;
            float b0 = bq[n0 + w], b1 = bq[n0 + w + 1];
            int m_lo = warp_m * 32 + mt * 16 + g;   // local row
            Ct[m_lo * CTP + w]       = __uint_as_float(f2tf32(acc[mt][nt][0] + b0));
            Ct[m_lo * CTP + w + 1]   = __uint_as_float(f2tf32(acc[mt][nt][1] + b1));
            Ct[(m_lo + 8) * CTP + w]     = __uint_as_float(f2tf32(acc[mt][nt][2] + b0));
            Ct[(m_lo + 8) * CTP + w + 1] = __uint_as_float(f2tf32(acc[mt][nt][3] + b1));
        }
    }
    __syncthreads();

    if (sel == 2) {   // V: [h][w][blk64(s) | pmap(s%64)]
        float* vtp = g_v + (size_t)head * WHEAD * S_LEN;
#pragma unroll
        for (int it = 0; it < 8; ++it) {
            int idx = tid + it * 256;          // 0..2047
            int w = idx >> 5, sc = idx & 31;   // w 0..63, s-chunk 0..31
            int p0 = sc * 4;
            float4 o;
            o.x = Ct[(((p0 + 0) & ~63) | pmap((p0 + 0) & 63)) * CTP + w];
            o.y = Ct[(((p0 + 1) & ~63) | pmap((p0 + 1) & 63)) * CTP + w];
            o.z = Ct[(((p0 + 2) & ~63) | pmap((p0 + 2) & 63)) * CTP + w];
            o.w = Ct[(((p0 + 3) & ~63) | pmap((p0 + 3) & 63)) * CTP + w];
            *(float4*)&vtp[(size_t)w * S_LEN + m0 + p0] = o;
        }
    } else {          // Q/K: [h][s][pmap(w)]
        float* dst = (sel == 0) ? g_q : g_k;
#pragma unroll
        for (int it = 0; it < 8; ++it) {
            int idx = tid + it * 256;
            int m = idx >> 4, c4 = idx & 15;
            float4 o;
            o.x = Ct[m * CTP + pmap(c4 * 4 + 0)];
            o.y = Ct[m * CTP + pmap(c4 * 4 + 1)];
            o.z = Ct[m * CTP + pmap(c4 * 4 + 2)];
            o.w = Ct[m * CTP + pmap(c4 * 4 + 3)];
            *(float4*)&dst[((size_t)head * S_LEN + m0 + m) * WHEAD + c4 * 4] = o;
        }
    }
}

// =============== Kernel 2: flash attention (tf32, LDS.128 fragments) ===============
#define SM_Q   0
#define SM_K   (128 * 64)
#define SM_V   (SM_K + 64 * 64)
#define SM_AM  (SM_V + 64 * 64)
#define ATTN_SMEM_F (SM_AM + 2 * 64)
#define ATTN_SMEM_BYTES (ATTN_SMEM_F * 4)   // 66048 B -> 3 CTAs/SM

#define LOG2E 1.4426950408889634f
#define SCL   (0.125f * LOG2E)
#define AMC   (10000.0f * LOG2E)

__global__ __launch_bounds__(128, 3) void attn_tc(
    const float* __restrict__ mask, float* __restrict__ out)
{
    extern __shared__ float smf[];

    const int tid = threadIdx.x;
    const int wid = tid >> 5;
    const int lane = tid & 31;
    const int g = lane >> 2;
    const int c = lane & 3;
    const int srcA = (lane & 28) | (c >> 1);
    const int srcB = srcA + 2;
    const int r0 = blockIdx.x * 128;
    const int head = blockIdx.y;

    const float* qh = g_q + (size_t)head * S_LEN * WHEAD;
    const float* kh = g_k + (size_t)head * S_LEN * WHEAD;
    const float* vt = g_v + (size_t)head * WHEAD * S_LEN;

    const int rowL = tid >> 4;           // 0..7 (+8r)
    const int c4L = tid & 15;            // 16B chunk

    // ---- prologue: Q(128x64), K(0), V(0), mask(0) ----
#pragma unroll
    for (int r = 0; r < 16; ++r) {
        int row = rowL + r * 8;
        cpa16(&smf[SM_Q + row * 64 + swz(row, c4L)],
              &qh[(size_t)(r0 + row) * WHEAD + c4L * 4]);
    }
#pragma unroll
    for (int r = 0; r < 8; ++r) {
        int row = rowL + r * 8;
        cpa16(&smf[SM_K + row * 64 + swz(row, c4L)],
              &kh[(size_t)row * WHEAD + c4L * 4]);
        cpa16(&smf[SM_V + row * 64 + swz(row, c4L)],
              &vt[(size_t)row * S_LEN + c4L * 4]);
    }
    if (tid < 16) cpa16(&smf[SM_AM + tid * 4], &mask[tid * 4]);
    CPA_COMMIT();

    float oacc[2][8][4];
#pragma unroll
    for (int mt = 0; mt < 2; ++mt)
#pragma unroll
        for (int nt = 0; nt < 8; ++nt)
#pragma unroll
            for (int i = 0; i < 4; ++i) oacc[mt][nt][i] = 0.0f;
    float mrow[2][2], lrow[2][2];
#pragma unroll
    for (int mt = 0; mt < 2; ++mt) {
        mrow[mt][0] = mrow[mt][1] = -1e30f;
        lrow[mt][0] = lrow[mt][1] = 0.0f;
    }

    CPA_WAIT0();
    __syncthreads();

    for (int t = 0; t < S_LEN / 64; ++t) {
        // ---- S = Q K^T ----
        float sacc[2][8][4];
#pragma unroll
        for (int mt = 0; mt < 2; ++mt)
#pragma unroll
            for (int nt = 0; nt < 8; ++nt)
#pragma unroll
                for (int i = 0; i < 4; ++i) sacc[mt][nt][i] = 0.0f;

#pragma unroll
        for (int p = 0; p < 4; ++p) {
            const int ch = p * 4 + c;
            float4 qa[2][2];
#pragma unroll
            for (int mt = 0; mt < 2; ++mt) {
                int mr = wid * 32 + mt * 16 + g;
                qa[mt][0] = *(const float4*)&smf[SM_Q + mr * 64 + swz(mr, ch)];
                qa[mt][1] = *(const float4*)&smf[SM_Q + (mr + 8) * 64 + swz(mr + 8, ch)];
            }
#pragma unroll
            for (int nt = 0; nt < 8; ++nt) {
                int kr = nt * 8 + g;
                float4 kb = *(const float4*)&smf[SM_K + kr * 64 + swz(kr, ch)];
#pragma unroll
                for (int mt = 0; mt < 2; ++mt) {
                    mma_tf32(sacc[mt][nt][0], sacc[mt][nt][1], sacc[mt][nt][2], sacc[mt][nt][3],
                             __float_as_uint(qa[mt][0].x), __float_as_uint(qa[mt][1].x),
                             __float_as_uint(qa[mt][0].y), __float_as_uint(qa[mt][1].y),
                             __float_as_uint(kb.x), __float_as_uint(kb.y));
                    mma_tf32(sacc[mt][nt][0], sacc[mt][nt][1], sacc[mt][nt][2], sacc[mt][nt][3],
                             __float_as_uint(qa[mt][0].z), __float_as_uint(qa[mt][1].z),
                             __float_as_uint(qa[mt][0].w), __float_as_uint(qa[mt][1].w),
                             __float_as_uint(kb.z), __float_as_uint(kb.w));
                }
            }
        }

        __syncthreads();   // all warps done reading K
        if (t + 1 < S_LEN / 64) {
            const int t1 = (t + 1) * 64;
#pragma unroll
            for (int r = 0; r < 8; ++r) {
                int row = rowL + r * 8;
                cpa16(&smf[SM_K + row * 64 + swz(row, c4L)],
                      &kh[(size_t)(t1 + row) * WHEAD + c4L * 4]);
            }
            if (tid < 16) cpa16(&smf[SM_AM + ((t + 1) & 1) * 64 + tid * 4], &mask[t1 + tid * 4]);
        }
        CPA_COMMIT();

        // ---- additive mask (log2 domain); S cols are natural j ----
        float amv[8][2];
#pragma unroll
        for (int nt = 0; nt < 8; ++nt) {
            float m0v = smf[SM_AM + (t & 1) * 64 + nt * 8 + 2 * c];
            float m1v = smf[SM_AM + (t & 1) * 64 + nt * 8 + 2 * c + 1];
            amv[nt][0] = fmaf(m0v, AMC, -AMC);
            amv[nt][1] = fmaf(m1v, AMC, -AMC);
        }

        // ---- online softmax per m-tile ----
#pragma unroll
        for (int mt = 0; mt < 2; ++mt) {
            float vmax_lo = -1e30f, vmax_hi = -1e30f;
#pragma unroll
            for (int nt = 0; nt < 8; ++nt) {
                sacc[mt][nt][0] = fmaf(sacc[mt][nt][0], SCL, amv[nt][0]);
                sacc[mt][nt][1] = fmaf(sacc[mt][nt][1], SCL, amv[nt][1]);
                sacc[mt][nt][2] = fmaf(sacc[mt][nt][2], SCL, amv[nt][0]);
                sacc[mt][nt][3] = fmaf(sacc[mt][nt][3], SCL, amv[nt][1]);
                vmax_lo = fmaxf(vmax_lo, fmaxf(sacc[mt][nt][0], sacc[mt][nt][1]));
                vmax_hi = fmaxf(vmax_hi, fmaxf(sacc[mt][nt][2], sacc[mt][nt][3]));
            }
#pragma unroll
            for (int off = 1; off <= 2; off <<= 1) {
                vmax_lo = fmaxf(vmax_lo, __shfl_xor_sync(0xffffffffu, vmax_lo, off));
                vmax_hi = fmaxf(vmax_hi, __shfl_xor_sync(0xffffffffu, vmax_hi, off));
            }
            float mn_lo = fmaxf(mrow[mt][0], vmax_lo);
            float mn_hi = fmaxf(mrow[mt][1], vmax_hi);
            float corr_lo = ex2(mrow[mt][0] - mn_lo);
            float corr_hi = ex2(mrow[mt][1] - mn_hi);
            float rs_lo = 0.0f, rs_hi = 0.0f;
#pragma unroll
            for (int nt = 0; nt < 8; ++nt) {
                sacc[mt][nt][0] = ex2(sacc[mt][nt][0] - mn_lo);
                sacc[mt][nt][1] = ex2(sacc[mt][nt][1] - mn_lo);
                sacc[mt][nt][2] = ex2(sacc[mt][nt][2] - mn_hi);
                sacc[mt][nt][3] = ex2(sacc[mt][nt][3] - mn_hi);
                rs_lo += sacc[mt][nt][0] + sacc[mt][nt][1];
                rs_hi += sacc[mt][nt][2] + sacc[mt][nt][3];
            }
#pragma unroll
            for (int off = 1; off <= 2; off <<= 1) {
                rs_lo += __shfl_xor_sync(0xffffffffu, rs_lo, off);
                rs_hi += __shfl_xor_sync(0xffffffffu, rs_hi, off);
            }
            lrow[mt][0] = lrow[mt][0] * corr_lo + rs_lo;
            lrow[mt][1] = lrow[mt][1] * corr_hi + rs_hi;
            mrow[mt][0] = mn_lo; mrow[mt][1] = mn_hi;
#pragma unroll
            for (int nt = 0; nt < 8; ++nt) {
                oacc[mt][nt][0] *= corr_lo; oacc[mt][nt][1] *= corr_lo;
                oacc[mt][nt][2] *= corr_hi; oacc[mt][nt][3] *= corr_hi;
            }
        }

        // ---- P -> tf32 bits in place ----
#pragma unroll
        for (int mt = 0; mt < 2; ++mt)
#pragma unroll
            for (int nt = 0; nt < 8; ++nt)
#pragma unroll
                for (int i = 0; i < 4; ++i)
                    sacc[mt][nt][i] = __uint_as_float(f2tf32(sacc[mt][nt][i]));

        // ---- O += P V ; A-frags via intra-quad shuffles, V B-frags LDS.128 ----
#pragma unroll
        for (int p = 0; p < 4; ++p) {
            const int ch = p * 4 + c;
            uint32_t af[2][2][4];
#pragma unroll
            for (int half = 0; half < 2; ++half) {
                int kk = 2 * p + half;
#pragma unroll
                for (int mt = 0; mt < 2; ++mt) {
                    uint32_t p0 = __float_as_uint(sacc[mt][kk][0]);
                    uint32_t p1 = __float_as_uint(sacc[mt][kk][1]);
                    uint32_t p2 = __float_as_uint(sacc[mt][kk][2]);
                    uint32_t p3 = __float_as_uint(sacc[mt][kk][3]);
                    uint32_t x0 = __shfl_sync(0xffffffffu, p0, srcA);
                    uint32_t x1 = __shfl_sync(0xffffffffu, p1, srcA);
                    uint32_t y0 = __shfl_sync(0xffffffffu, p0, srcB);
                    uint32_t y1 = __shfl_sync(0xffffffffu, p1, srcB);
                    af[half][mt][0] = (c & 1) ? x1 : x0;
                    af[half][mt][2] = (c & 1) ? y1 : y0;
                    uint32_t x2 = __shfl_sync(0xffffffffu, p2, srcA);
                    uint32_t x3 = __shfl_sync(0xffffffffu, p3, srcA);
                    uint32_t y2 = __shfl_sync(0xffffffffu, p2, srcB);
                    uint32_t y3 = __shfl_sync(0xffffffffu, p3, srcB);
                    af[half][mt][1] = (c & 1) ? x3 : x2;
                    af[half][mt][3] = (c & 1) ? y3 : y2;
                }
            }
#pragma unroll
            for (int nt = 0; nt < 8; ++nt) {
                int vr = nt * 8 + g;
                float4 vb = *(const float4*)&smf[SM_V + vr * 64 + swz(vr, ch)];
#pragma unroll
                for (int mt = 0; mt < 2; ++mt) {
                    mma_tf32(oacc[mt][nt][0], oacc[mt][nt][1], oacc[mt][nt][2], oacc[mt][nt][3],
                             af[0][mt][0], af[0][mt][1], af[0][mt][2], af[0][mt][3],
                             __float_as_uint(vb.x), __float_as_uint(vb.y));
                    mma_tf32(oacc[mt][nt][0], oacc[mt][nt][1], oacc[mt][nt][2], oacc[mt][nt][3],
                             af[1][mt][0], af[1][mt][1], af[1][mt][2], af[1][mt][3],
                             __float_as_uint(vb.z), __float_as_uint(vb.w));
                }
            }
        }

        __syncthreads();   // all warps done reading V
        if (t + 1 < S_LEN / 64) {
            const int t1 = (t + 1) * 64;
#pragma unroll
            for (int r = 0; r < 8; ++r) {
                int row = rowL + r * 8;
                cpa16(&smf[SM_V + row * 64 + swz(row, c4L)],
                      &vt[(size_t)row * S_LEN + t1 + c4L * 4]);
            }
        }
        CPA_COMMIT();
        CPA_WAIT0();
        __syncthreads();
    }

    // ---- epilogue (natural w cols) ----
#pragma unroll
    for (int mt = 0; mt < 2; ++mt) {
        float inv_lo = 1.0f / lrow[mt][0];
        float inv_hi = 1.0f / lrow[mt][1];
        int row_lo = r0 + wid * 32 + mt * 16 + g;
#pragma unroll
        for (int nt = 0; nt < 8; ++nt) {
            int col = head * WHEAD + nt * 8 + 2 * c;
            float2 lo = make_float2(oacc[mt][nt][0] * inv_lo, oacc[mt][nt][1] * inv_lo);
            float2 hi = make_float2(oacc[mt][nt][2] * inv_hi, oacc[mt][nt][3] * inv_hi);
            *(float2*)&out[(size_t)row_lo * D_MODEL + col] = lo;
            *(float2*)&out[(size_t)(row_lo + 8) * D_MODEL + col] = hi;
        }
    }
}

// ---------------- launch ----------------
extern "C" void kernel_launch(void* const* d_in, const int* in_sizes, int n_in,
                              void* d_out, int out_size)
{
    const float* x    = (const float*)d_in[0];
    const float* mask = (const float*)d_in[1];
    const float* Wq   = (const float*)d_in[2];
    const float* bq   = (const float*)d_in[3];
    float* out = (float*)d_out;

    dim3 gGemm(N_QKV / 64, S_LEN / 128);         // (36, 32)
    qkv_gemm_tc<<<gGemm, 256>>>(x, Wq, bq);

    cudaFuncSetAttribute(attn_tc,
                         cudaFuncAttributeMaxDynamicSharedMemorySize,
                         ATTN_SMEM_BYTES);
    dim3 gAttn(S_LEN / 128, NHEAD);              // (32, 12)
    attn_tc<<<gAttn, 128, ATTN_SMEM_BYTES>>>(mask, out);
}

// round 8
// speedup vs baseline: 1.7723x; 1.1526x over previous
#include <cuda_runtime.h>
#include <cuda_bf16.h>
#include <cstdint>

#define S_LEN 4096
#define D_MODEL 768
#define NHEAD 12
#define WHEAD 64
#define N_QKV 2304

// ---------------- scratch: tf32 bit patterns ----------------
__device__ float g_q[NHEAD * S_LEN * WHEAD];    // [h][s][w]
__device__ float g_kt[NHEAD * WHEAD * S_LEN];   // [h][w][s]  (transposed)
__device__ float g_v[NHEAD * S_LEN * WHEAD];    // [h][s][w]

// ---------------- helpers ----------------
__device__ __forceinline__ uint32_t f2tf32(float x) {
    uint32_t u;
    asm("cvt.rna.tf32.f32 %0, %1;" : "=r"(u) : "f"(x));
    return u;
}
__device__ __forceinline__ float ex2(float x) {
    float y;
    asm("ex2.approx.f32 %0, %1;" : "=f"(y) : "f"(x));
    return y;
}

__device__ __forceinline__ void mma_tf32(
    float& d0, float& d1, float& d2, float& d3,
    uint32_t a0, uint32_t a1, uint32_t a2, uint32_t a3,
    uint32_t b0, uint32_t b1)
{
    asm volatile(
        "mma.sync.aligned.m16n8k8.row.col.f32.tf32.tf32.f32 "
        "{%0,%1,%2,%3},{%4,%5,%6,%7},{%8,%9},{%0,%1,%2,%3};"
        : "+f"(d0), "+f"(d1), "+f"(d2), "+f"(d3)
        : "r"(a0), "r"(a1), "r"(a2), "r"(a3), "r"(b0), "r"(b1));
}

__device__ __forceinline__ void cpa16(void* s, const void* g) {
    uint32_t sa = (uint32_t)__cvta_generic_to_shared(s);
    asm volatile("cp.async.cg.shared.global [%0], [%1], 16;" :: "r"(sa), "l"(g));
}
#define CPA_COMMIT() asm volatile("cp.async.commit_group;" ::: "memory")
#define CPA_WAIT0()  asm volatile("cp.async.wait_group 0;" ::: "memory")
#define CPA_WAIT1()  asm volatile("cp.async.wait_group 1;" ::: "memory")

// =============== Kernel 1: QKV GEMM (tf32, cp.async double-buffered) ===============
#define GAP 36   // A pitch (mod 32 == 4)
#define GBP 72   // B pitch (mod 32 == 8)

__global__ __launch_bounds__(256) void qkv_gemm_tc(
    const float* __restrict__ X, const float* __restrict__ Wq,
    const float* __restrict__ bq)
{
    __shared__ float As[2][128 * GAP];
    __shared__ float Bs[2][32 * GBP];

    const int tid = threadIdx.x;
    const int wid = tid >> 5;
    const int lane = tid & 31;
    const int g = lane >> 2;
    const int c = lane & 3;
    const int warp_m = wid >> 1;
    const int warp_n = wid & 1;
    const int m0 = blockIdx.y * 128;
    const int n0 = blockIdx.x * 64;

    float acc[2][4][4];
#pragma unroll
    for (int mt = 0; mt < 2; ++mt)
#pragma unroll
        for (int nt = 0; nt < 4; ++nt)
#pragma unroll
            for (int i = 0; i < 4; ++i) acc[mt][nt][i] = 0.0f;

    const int rowA = tid >> 3, c4A = tid & 7;
    const int rowB = tid >> 4, c4B = tid & 15;

    auto issue = [&](int k0, int buf) {
#pragma unroll
        for (int r = 0; r < 4; ++r) {
            int row = rowA + r * 32;
            cpa16(&As[buf][row * GAP + c4A * 4],
                  &X[(size_t)(m0 + row) * D_MODEL + k0 + c4A * 4]);
        }
#pragma unroll
        for (int r = 0; r < 2; ++r) {
            int row = rowB + r * 16;
            cpa16(&Bs[buf][row * GBP + c4B * 4],
                  &Wq[(size_t)(k0 + row) * N_QKV + n0 + c4B * 4]);
        }
        CPA_COMMIT();
    };

    issue(0, 0);
    for (int i = 0; i < 24; ++i) {
        CPA_WAIT0();
        __syncthreads();
        if (i + 1 < 24) issue((i + 1) * 32, (i + 1) & 1);
        const float* A = As[i & 1];
        const float* B = Bs[i & 1];
#pragma unroll
        for (int kk = 0; kk < 4; ++kk) {
            uint32_t af[2][4];
#pragma unroll
            for (int mt = 0; mt < 2; ++mt) {
                int mr = warp_m * 32 + mt * 16 + g;
                af[mt][0] = f2tf32(A[mr * GAP + kk * 8 + c]);
                af[mt][1] = f2tf32(A[(mr + 8) * GAP + kk * 8 + c]);
                af[mt][2] = f2tf32(A[mr * GAP + kk * 8 + c + 4]);
                af[mt][3] = f2tf32(A[(mr + 8) * GAP + kk * 8 + c + 4]);
            }
#pragma unroll
            for (int nt = 0; nt < 4; ++nt) {
                int nc = warp_n * 32 + nt * 8 + g;
                uint32_t b0 = f2tf32(B[(kk * 8 + c) * GBP + nc]);
                uint32_t b1 = f2tf32(B[(kk * 8 + c + 4) * GBP + nc]);
#pragma unroll
                for (int mt = 0; mt < 2; ++mt)
                    mma_tf32(acc[mt][nt][0], acc[mt][nt][1], acc[mt][nt][2], acc[mt][nt][3],
                             af[mt][0], af[mt][1], af[mt][2], af[mt][3], b0, b1);
            }
        }
        __syncthreads();
    }

    // epilogue: bias, convert to tf32 bits, scatter (K transposed)
    const int sel = n0 / D_MODEL;
    const int head = (n0 % D_MODEL) / WHEAD;

#pragma unroll
    for (int mt = 0; mt < 2; ++mt) {
#pragma unroll
        for (int nt = 0; nt < 4; ++nt) {
            int w = warp_n * 32 + nt * 8 + 2 * c;
            float b0 = bq[n0 + w], b1 = bq[n0 + w + 1];
            int m_lo = m0 + warp_m * 32 + mt * 16 + g;
            float v00 = __uint_as_float(f2tf32(acc[mt][nt][0] + b0));
            float v01 = __uint_as_float(f2tf32(acc[mt][nt][1] + b1));
            float v10 = __uint_as_float(f2tf32(acc[mt][nt][2] + b0));
            float v11 = __uint_as_float(f2tf32(acc[mt][nt][3] + b1));
            if (sel == 1) {   // K: [h][w][s]
                float* kt = g_kt + (size_t)head * WHEAD * S_LEN;
                kt[(size_t)w * S_LEN + m_lo] = v00;
                kt[(size_t)(w + 1) * S_LEN + m_lo] = v01;
                kt[(size_t)w * S_LEN + m_lo + 8] = v10;
                kt[(size_t)(w + 1) * S_LEN + m_lo + 8] = v11;
            } else {
                float* dst = (sel == 0) ? g_q : g_v;
                *(float2*)&dst[((size_t)head * S_LEN + m_lo) * WHEAD + w] = make_float2(v00, v01);
                *(float2*)&dst[((size_t)head * S_LEN + m_lo + 8) * WHEAD + w] = make_float2(v10, v11);
            }
        }
    }
}

// =============== Kernel 2: flash attention (tf32, static-max softmax) ===============
#define QPITCH 68   // mod 32 == 4
#define KPITCH 72   // mod 32 == 8
#define VPITCH 72
#define SM_Q   0
#define SM_K   (128 * QPITCH)
#define SM_V   (SM_K + 64 * KPITCH)
#define SM_AM  (SM_V + 64 * VPITCH)
#define ATTN_SMEM_U32 (SM_AM + 2 * 64)
#define ATTN_SMEM_BYTES (ATTN_SMEM_U32 * 4)   // ~72 KB

#define LOG2E 1.4426950408889634f
#define SCL   (0.125f * LOG2E)
#define AMC   (10000.0f * LOG2E)

__global__ __launch_bounds__(128, 3) void attn_tc(
    const float* __restrict__ mask, float* __restrict__ out)
{
    extern __shared__ uint32_t sm[];
    float* smf = (float*)sm;

    const int tid = threadIdx.x;
    const int wid = tid >> 5;
    const int lane = tid & 31;
    const int g = lane >> 2;
    const int c = lane & 3;
    const int srcA = (lane & 28) | (c >> 1);
    const int srcB = srcA + 2;
    const int r0 = blockIdx.x * 128;
    const int head = blockIdx.y;

    const float* qh = g_q + (size_t)head * S_LEN * WHEAD;
    const float* kt = g_kt + (size_t)head * WHEAD * S_LEN;
    const float* vh = g_v + (size_t)head * S_LEN * WHEAD;

    const int rowL = tid >> 4, c4L = tid & 15;

    // ---- prologue: Q (128x64), K(0), V(0), mask(0) — one group ----
#pragma unroll
    for (int r = 0; r < 16; ++r) {
        int row = rowL + r * 8;
        cpa16(&sm[SM_Q + row * QPITCH + c4L * 4],
              &qh[(size_t)(r0 + row) * WHEAD + c4L * 4]);
    }
#pragma unroll
    for (int r = 0; r < 8; ++r) {
        int w = rowL + r * 8;
        cpa16(&sm[SM_K + w * KPITCH + c4L * 4], &kt[(size_t)w * S_LEN + c4L * 4]);
        cpa16(&sm[SM_V + w * VPITCH + c4L * 4], &vh[(size_t)w * WHEAD + c4L * 4]);
    }
    if (tid < 16) cpa16(&sm[SM_AM + tid * 4], &mask[tid * 4]);
    CPA_COMMIT();

    float oacc[2][8][4];
#pragma unroll
    for (int mt = 0; mt < 2; ++mt)
#pragma unroll
        for (int nt = 0; nt < 8; ++nt)
#pragma unroll
            for (int i = 0; i < 4; ++i) oacc[mt][nt][i] = 0.0f;
    float lrow[2][2];   // per-lane partial row sums; quad-reduced in epilogue
    lrow[0][0] = lrow[0][1] = lrow[1][0] = lrow[1][1] = 0.0f;

    CPA_WAIT0();
    __syncthreads();

    for (int t = 0; t < S_LEN / 64; ++t) {
        // ---- S = Q K^T : 32 rows x 64 cols per warp ----
        float sacc[2][8][4];
#pragma unroll
        for (int mt = 0; mt < 2; ++mt)
#pragma unroll
            for (int nt = 0; nt < 8; ++nt)
#pragma unroll
                for (int i = 0; i < 4; ++i) sacc[mt][nt][i] = 0.0f;

#pragma unroll
        for (int kk = 0; kk < 8; ++kk) {
            uint32_t af[2][4];
#pragma unroll
            for (int mt = 0; mt < 2; ++mt) {
                int mr = wid * 32 + mt * 16 + g;
                af[mt][0] = sm[SM_Q + mr * QPITCH + kk * 8 + c];
                af[mt][1] = sm[SM_Q + (mr + 8) * QPITCH + kk * 8 + c];
                af[mt][2] = sm[SM_Q + mr * QPITCH + kk * 8 + c + 4];
                af[mt][3] = sm[SM_Q + (mr + 8) * QPITCH + kk * 8 + c + 4];
            }
#pragma unroll
            for (int nt = 0; nt < 8; ++nt) {
                uint32_t b0 = sm[SM_K + (kk * 8 + c) * KPITCH + nt * 8 + g];
                uint32_t b1 = sm[SM_K + (kk * 8 + c + 4) * KPITCH + nt * 8 + g];
#pragma unroll
                for (int mt = 0; mt < 2; ++mt)
                    mma_tf32(sacc[mt][nt][0], sacc[mt][nt][1], sacc[mt][nt][2], sacc[mt][nt][3],
                             af[mt][0], af[mt][1], af[mt][2], af[mt][3], b0, b1);
            }
        }

        __syncthreads();   // all warps done reading K
        // ---- prefetch K(t+1) + mask(t+1): group overlaps softmax + PV ----
        if (t + 1 < S_LEN / 64) {
            const int t1 = (t + 1) * 64;
#pragma unroll
            for (int r = 0; r < 8; ++r) {
                int w = rowL + r * 8;
                cpa16(&sm[SM_K + w * KPITCH + c4L * 4], &kt[(size_t)w * S_LEN + t1 + c4L * 4]);
            }
            if (tid < 16) cpa16(&sm[SM_AM + ((t + 1) & 1) * 64 + tid * 4], &mask[t1 + tid * 4]);
        }
        CPA_COMMIT();

        // ---- static-max softmax: p = ex2(s*SCL + am), accumulate partial sums ----
        {
            float amv[8][2];
#pragma unroll
            for (int nt = 0; nt < 8; ++nt) {
                float m0v = smf[SM_AM + (t & 1) * 64 + nt * 8 + 2 * c];
                float m1v = smf[SM_AM + (t & 1) * 64 + nt * 8 + 2 * c + 1];
                amv[nt][0] = fmaf(m0v, AMC, -AMC);
                amv[nt][1] = fmaf(m1v, AMC, -AMC);
            }
#pragma unroll
            for (int mt = 0; mt < 2; ++mt) {
#pragma unroll
                for (int nt = 0; nt < 8; ++nt) {
                    float p0 = ex2(fmaf(sacc[mt][nt][0], SCL, amv[nt][0]));
                    float p1 = ex2(fmaf(sacc[mt][nt][1], SCL, amv[nt][1]));
                    float p2 = ex2(fmaf(sacc[mt][nt][2], SCL, amv[nt][0]));
                    float p3 = ex2(fmaf(sacc[mt][nt][3], SCL, amv[nt][1]));
                    lrow[mt][0] += p0 + p1;
                    lrow[mt][1] += p2 + p3;
                    sacc[mt][nt][0] = __uint_as_float(f2tf32(p0));
                    sacc[mt][nt][1] = __uint_as_float(f2tf32(p1));
                    sacc[mt][nt][2] = __uint_as_float(f2tf32(p2));
                    sacc[mt][nt][3] = __uint_as_float(f2tf32(p3));
                }
            }
        }

        // V(t) is guaranteed ready: its group completed before this iteration's
        // trailing wait last time around (prologue covers t=0).

        // ---- O += P V ; A-frags via intra-quad shuffles ----
#pragma unroll
        for (int kk = 0; kk < 8; ++kk) {
            uint32_t af[2][4];
#pragma unroll
            for (int mt = 0; mt < 2; ++mt) {
                uint32_t p0 = __float_as_uint(sacc[mt][kk][0]);
                uint32_t p1 = __float_as_uint(sacc[mt][kk][1]);
                uint32_t p2 = __float_as_uint(sacc[mt][kk][2]);
                uint32_t p3 = __float_as_uint(sacc[mt][kk][3]);
                uint32_t x0 = __shfl_sync(0xffffffffu, p0, srcA);
                uint32_t x1 = __shfl_sync(0xffffffffu, p1, srcA);
                uint32_t y0 = __shfl_sync(0xffffffffu, p0, srcB);
                uint32_t y1 = __shfl_sync(0xffffffffu, p1, srcB);
                af[mt][0] = (c & 1) ? x1 : x0;
                af[mt][2] = (c & 1) ? y1 : y0;
                uint32_t x2 = __shfl_sync(0xffffffffu, p2, srcA);
                uint32_t x3 = __shfl_sync(0xffffffffu, p3, srcA);
                uint32_t y2 = __shfl_sync(0xffffffffu, p2, srcB);
                uint32_t y3 = __shfl_sync(0xffffffffu, p3, srcB);
                af[mt][1] = (c & 1) ? x3 : x2;
                af[mt][3] = (c & 1) ? y3 : y2;
            }
#pragma unroll
            for (int nt = 0; nt < 8; ++nt) {
                uint32_t b0 = sm[SM_V + (kk * 8 + c) * VPITCH + nt * 8 + g];
                uint32_t b1 = sm[SM_V + (kk * 8 + c + 4) * VPITCH + nt * 8 + g];
#pragma unroll
                for (int mt = 0; mt < 2; ++mt)
                    mma_tf32(oacc[mt][nt][0], oacc[mt][nt][1], oacc[mt][nt][2], oacc[mt][nt][3],
                             af[mt][0], af[mt][1], af[mt][2], af[mt][3], b0, b1);
            }
        }

        __syncthreads();   // all warps done reading V
        // ---- prefetch V(t+1): its group overlaps trailing wait + next S + softmax ----
        if (t + 1 < S_LEN / 64) {
            const int t1 = (t + 1) * 64;
#pragma unroll
            for (int r = 0; r < 8; ++r) {
                int j = rowL + r * 8;
                cpa16(&sm[SM_V + j * VPITCH + c4L * 4],
                      &vh[(size_t)(t1 + j) * WHEAD + c4L * 4]);
            }
        }
        CPA_COMMIT();
        CPA_WAIT1();       // K(t+1) (older group) complete; V(t+1) may still fly
        __syncthreads();
    }

    // ---- epilogue: quad-reduce l, normalize, write ----
#pragma unroll
    for (int mt = 0; mt < 2; ++mt) {
#pragma unroll
        for (int off = 1; off <= 2; off <<= 1) {
            lrow[mt][0] += __shfl_xor_sync(0xffffffffu, lrow[mt][0], off);
            lrow[mt][1] += __shfl_xor_sync(0xffffffffu, lrow[mt][1], off);
        }
        float inv_lo = 1.0f / lrow[mt][0];
        float inv_hi = 1.0f / lrow[mt][1];
        int row_lo = r0 + wid * 32 + mt * 16 + g;
#pragma unroll
        for (int nt = 0; nt < 8; ++nt) {
            int col = head * WHEAD + nt * 8 + 2 * c;
            float2 lo = make_float2(oacc[mt][nt][0] * inv_lo, oacc[mt][nt][1] * inv_lo);
            float2 hi = make_float2(oacc[mt][nt][2] * inv_hi, oacc[mt][nt][3] * inv_hi);
            *(float2*)&out[(size_t)row_lo * D_MODEL + col] = lo;
            *(float2*)&out[(size_t)(row_lo + 8) * D_MODEL + col] = hi;
        }
    }
}

// ---------------- launch ----------------
extern "C" void kernel_launch(void* const* d_in, const int* in_sizes, int n_in,
                              void* d_out, int out_size)
{
    const float* x    = (const float*)d_in[0];
    const float* mask = (const float*)d_in[1];
    const float* Wq   = (const float*)d_in[2];
    const float* bq   = (const float*)d_in[3];
    float* out = (float*)d_out;

    dim3 gGemm(N_QKV / 64, S_LEN / 128);         // (36, 32)
    qkv_gemm_tc<<<gGemm, 256>>>(x, Wq, bq);

    cudaFuncSetAttribute(attn_tc,
                         cudaFuncAttributeMaxDynamicSharedMemorySize,
                         ATTN_SMEM_BYTES);
    dim3 gAttn(S_LEN / 128, NHEAD);              // (32, 12)
    attn_tc<<<gAttn, 128, ATTN_SMEM_BYTES>>>(mask, out);
}

// round 10
// speedup vs baseline: 1.7909x; 1.0105x over previous
#include <cuda_runtime.h>
#include <cuda_bf16.h>
#include <cstdint>

#define S_LEN 4096
#define D_MODEL 768
#define NHEAD 12
#define WHEAD 64
#define N_QKV 2304

// ---------------- scratch: tf32 bit patterns ----------------
__device__ float g_q[NHEAD * S_LEN * WHEAD];    // [h][s][w]
__device__ float g_kt[NHEAD * WHEAD * S_LEN];   // [h][w][s]  (transposed)
__device__ float g_v[NHEAD * S_LEN * WHEAD];    // [h][s][w]

// ---------------- helpers ----------------
__device__ __forceinline__ uint32_t f2tf32(float x) {
    uint32_t u;
    asm("cvt.rna.tf32.f32 %0, %1;" : "=r"(u) : "f"(x));
    return u;
}
__device__ __forceinline__ float ex2(float x) {
    float y;
    asm("ex2.approx.f32 %0, %1;" : "=f"(y) : "f"(x));
    return y;
}

__device__ __forceinline__ void mma_tf32(
    float& d0, float& d1, float& d2, float& d3,
    uint32_t a0, uint32_t a1, uint32_t a2, uint32_t a3,
    uint32_t b0, uint32_t b1)
{
    asm volatile(
        "mma.sync.aligned.m16n8k8.row.col.f32.tf32.tf32.f32 "
        "{%0,%1,%2,%3},{%4,%5,%6,%7},{%8,%9},{%0,%1,%2,%3};"
        : "+f"(d0), "+f"(d1), "+f"(d2), "+f"(d3)
        : "r"(a0), "r"(a1), "r"(a2), "r"(a3), "r"(b0), "r"(b1));
}

__device__ __forceinline__ void cpa16(void* s, const void* g) {
    uint32_t sa = (uint32_t)__cvta_generic_to_shared(s);
    asm volatile("cp.async.cg.shared.global [%0], [%1], 16;" :: "r"(sa), "l"(g));
}
#define CPA_COMMIT() asm volatile("cp.async.commit_group;" ::: "memory")
#define CPA_WAIT0()  asm volatile("cp.async.wait_group 0;" ::: "memory")
#define CPA_WAIT1()  asm volatile("cp.async.wait_group 1;" ::: "memory")

// =============== Kernel 1: QKV GEMM (tf32, cp.async double-buffered) ===============
#define GAP 36
#define GBP 72

__global__ __launch_bounds__(256) void qkv_gemm_tc(
    const float* __restrict__ X, const float* __restrict__ Wq,
    const float* __restrict__ bq)
{
    __shared__ float As[2][128 * GAP];
    __shared__ float Bs[2][32 * GBP];

    const int tid = threadIdx.x;
    const int wid = tid >> 5;
    const int lane = tid & 31;
    const int g = lane >> 2;
    const int c = lane & 3;
    const int warp_m = wid >> 1;
    const int warp_n = wid & 1;
    const int m0 = blockIdx.y * 128;
    const int n0 = blockIdx.x * 64;

    float acc[2][4][4];
#pragma unroll
    for (int mt = 0; mt < 2; ++mt)
#pragma unroll
        for (int nt = 0; nt < 4; ++nt)
#pragma unroll
            for (int i = 0; i < 4; ++i) acc[mt][nt][i] = 0.0f;

    const int rowA = tid >> 3, c4A = tid & 7;
    const int rowB = tid >> 4, c4B = tid & 15;

    auto issue = [&](int k0, int buf) {
#pragma unroll
        for (int r = 0; r < 4; ++r) {
            int row = rowA + r * 32;
            cpa16(&As[buf][row * GAP + c4A * 4],
                  &X[(size_t)(m0 + row) * D_MODEL + k0 + c4A * 4]);
        }
#pragma unroll
        for (int r = 0; r < 2; ++r) {
            int row = rowB + r * 16;
            cpa16(&Bs[buf][row * GBP + c4B * 4],
                  &Wq[(size_t)(k0 + row) * N_QKV + n0 + c4B * 4]);
        }
        CPA_COMMIT();
    };

    issue(0, 0);
    for (int i = 0; i < 24; ++i) {
        CPA_WAIT0();
        __syncthreads();
        if (i + 1 < 24) issue((i + 1) * 32, (i + 1) & 1);
        const float* A = As[i & 1];
        const float* B = Bs[i & 1];
#pragma unroll
        for (int kk = 0; kk < 4; ++kk) {
            uint32_t af[2][4];
#pragma unroll
            for (int mt = 0; mt < 2; ++mt) {
                int mr = warp_m * 32 + mt * 16 + g;
                af[mt][0] = f2tf32(A[mr * GAP + kk * 8 + c]);
                af[mt][1] = f2tf32(A[(mr + 8) * GAP + kk * 8 + c]);
                af[mt][2] = f2tf32(A[mr * GAP + kk * 8 + c + 4]);
                af[mt][3] = f2tf32(A[(mr + 8) * GAP + kk * 8 + c + 4]);
            }
#pragma unroll
            for (int nt = 0; nt < 4; ++nt) {
                int nc = warp_n * 32 + nt * 8 + g;
                uint32_t b0 = f2tf32(B[(kk * 8 + c) * GBP + nc]);
                uint32_t b1 = f2tf32(B[(kk * 8 + c + 4) * GBP + nc]);
#pragma unroll
                for (int mt = 0; mt < 2; ++mt)
                    mma_tf32(acc[mt][nt][0], acc[mt][nt][1], acc[mt][nt][2], acc[mt][nt][3],
                             af[mt][0], af[mt][1], af[mt][2], af[mt][3], b0, b1);
            }
        }
        __syncthreads();
    }

    const int sel = n0 / D_MODEL;
    const int head = (n0 % D_MODEL) / WHEAD;

#pragma unroll
    for (int mt = 0; mt < 2; ++mt) {
#pragma unroll
        for (int nt = 0; nt < 4; ++nt) {
            int w = warp_n * 32 + nt * 8 + 2 * c;
            float b0 = bq[n0 + w], b1 = bq[n0 + w + 1];
            int m_lo = m0 + warp_m * 32 + mt * 16 + g;
            float v00 = __uint_as_float(f2tf32(acc[mt][nt][0] + b0));
            float v01 = __uint_as_float(f2tf32(acc[mt][nt][1] + b1));
            float v10 = __uint_as_float(f2tf32(acc[mt][nt][2] + b0));
            float v11 = __uint_as_float(f2tf32(acc[mt][nt][3] + b1));
            if (sel == 1) {   // K: [h][w][s]
                float* kt = g_kt + (size_t)head * WHEAD * S_LEN;
                kt[(size_t)w * S_LEN + m_lo] = v00;
                kt[(size_t)(w + 1) * S_LEN + m_lo] = v01;
                kt[(size_t)w * S_LEN + m_lo + 8] = v10;
                kt[(size_t)(w + 1) * S_LEN + m_lo + 8] = v11;
            } else {
                float* dst = (sel == 0) ? g_q : g_v;
                *(float2*)&dst[((size_t)head * S_LEN + m_lo) * WHEAD + w] = make_float2(v00, v01);
                *(float2*)&dst[((size_t)head * S_LEN + m_lo + 8) * WHEAD + w] = make_float2(v10, v11);
            }
        }
    }
}

// =============== Kernel 2: flash attention (BC=32, 4 CTAs/SM) ===============
#define QPITCH 68   // mod 32 == 4 -> conflict-free A reads
#define KP     40   // K^T tile pitch (s-cols 32+8); mod 32 == 8
#define VP     72   // V tile pitch (w 64+8); mod 32 == 8
#define SM_Q   0
#define SM_K   (128 * QPITCH)
#define SM_V   (SM_K + 64 * KP)
#define SM_AM  (SM_V + 32 * VP)
#define ATTN_SMEM_F (SM_AM + 2 * 32)
#define ATTN_SMEM_BYTES (ATTN_SMEM_F * 4)   // 54528 B -> 4 CTAs/SM

#define LOG2E 1.4426950408889634f
#define SCL   (0.125f * LOG2E)
#define AMC   (10000.0f * LOG2E)
#define NT_KV (S_LEN / 32)   // 128 kv tiles

__global__ __launch_bounds__(128, 4) void attn_tc(
    const float* __restrict__ mask, float* __restrict__ out)
{
    extern __shared__ uint32_t sm[];
    float* smf = (float*)sm;

    const int tid = threadIdx.x;
    const int wid = tid >> 5;
    const int lane = tid & 31;
    const int g = lane >> 2;
    const int c = lane & 3;
    const int srcA = (lane & 28) | (c >> 1);
    const int srcB = srcA + 2;
    const int r0 = blockIdx.x * 128;
    const int head = blockIdx.y;

    const float* qh = g_q + (size_t)head * S_LEN * WHEAD;
    const float* kt = g_kt + (size_t)head * WHEAD * S_LEN;
    const float* vh = g_v + (size_t)head * S_LEN * WHEAD;

    const int qRow = tid >> 4, qC4 = tid & 15;   // Q/V: 16-chunk rows
    const int kRow = tid >> 3, kC4 = tid & 7;    // K: 8-chunk rows (32 floats)

    auto issueK = [&](int t0) {
#pragma unroll
        for (int r = 0; r < 4; ++r) {
            int w = kRow + r * 16;
            cpa16(&sm[SM_K + w * KP + kC4 * 4], &kt[(size_t)w * S_LEN + t0 + kC4 * 4]);
        }
        if (tid < 8) cpa16(&sm[SM_AM + ((t0 >> 5) & 1) * 32 + tid * 4], &mask[t0 + tid * 4]);
    };
    auto issueV = [&](int t0) {
#pragma unroll
        for (int r = 0; r < 4; ++r) {
            int j = qRow + r * 8;
            cpa16(&sm[SM_V + j * VP + qC4 * 4], &vh[(size_t)(t0 + j) * WHEAD + qC4 * 4]);
        }
    };

    // ---- prologue: Q (128x64), K(0), V(0), mask(0) — one group ----
#pragma unroll
    for (int r = 0; r < 16; ++r) {
        int row = qRow + r * 8;
        cpa16(&sm[SM_Q + row * QPITCH + qC4 * 4],
              &qh[(size_t)(r0 + row) * WHEAD + qC4 * 4]);
    }
    issueK(0);
    issueV(0);
    CPA_COMMIT();

    float oacc[2][8][4];
#pragma unroll
    for (int mt = 0; mt < 2; ++mt)
#pragma unroll
        for (int nt = 0; nt < 8; ++nt)
#pragma unroll
            for (int i = 0; i < 4; ++i) oacc[mt][nt][i] = 0.0f;
    float lrow[2][2];
    lrow[0][0] = lrow[0][1] = lrow[1][0] = lrow[1][1] = 0.0f;

    CPA_WAIT0();
    __syncthreads();

    for (int t = 0; t < NT_KV; ++t) {
        // ---- S = Q K^T : 32 rows x 32 kv-cols per warp ----
        float sacc[2][4][4];
#pragma unroll
        for (int mt = 0; mt < 2; ++mt)
#pragma unroll
            for (int nt = 0; nt < 4; ++nt)
#pragma unroll
                for (int i = 0; i < 4; ++i) sacc[mt][nt][i] = 0.0f;

#pragma unroll
        for (int kk = 0; kk < 8; ++kk) {
            uint32_t af[2][4];
#pragma unroll
            for (int mt = 0; mt < 2; ++mt) {
                int mr = wid * 32 + mt * 16 + g;
                af[mt][0] = sm[SM_Q + mr * QPITCH + kk * 8 + c];
                af[mt][1] = sm[SM_Q + (mr + 8) * QPITCH + kk * 8 + c];
                af[mt][2] = sm[SM_Q + mr * QPITCH + kk * 8 + c + 4];
                af[mt][3] = sm[SM_Q + (mr + 8) * QPITCH + kk * 8 + c + 4];
            }
#pragma unroll
            for (int nt = 0; nt < 4; ++nt) {
                uint32_t b0 = sm[SM_K + (kk * 8 + c) * KP + nt * 8 + g];
                uint32_t b1 = sm[SM_K + (kk * 8 + c + 4) * KP + nt * 8 + g];
#pragma unroll
                for (int mt = 0; mt < 2; ++mt)
                    mma_tf32(sacc[mt][nt][0], sacc[mt][nt][1], sacc[mt][nt][2], sacc[mt][nt][3],
                             af[mt][0], af[mt][1], af[mt][2], af[mt][3], b0, b1);
            }
        }

        __syncthreads();                   // K readers done
        if (t + 1 < NT_KV) issueK((t + 1) * 32);
        CPA_COMMIT();                      // group = K(t+1)+mask(t+1)

        // ---- static-max softmax: p = ex2(s*SCL + am); raw fp32 bits to MMA ----
        {
            float amv[4][2];
#pragma unroll
            for (int nt = 0; nt < 4; ++nt) {
                float m0v = smf[SM_AM + (t & 1) * 32 + nt * 8 + 2 * c];
                float m1v = smf[SM_AM + (t & 1) * 32 + nt * 8 + 2 * c + 1];
                amv[nt][0] = fmaf(m0v, AMC, -AMC);
                amv[nt][1] = fmaf(m1v, AMC, -AMC);
            }
#pragma unroll
            for (int mt = 0; mt < 2; ++mt) {
#pragma unroll
                for (int nt = 0; nt < 4; ++nt) {
                    float p0 = ex2(fmaf(sacc[mt][nt][0], SCL, amv[nt][0]));
                    float p1 = ex2(fmaf(sacc[mt][nt][1], SCL, amv[nt][1]));
                    float p2 = ex2(fmaf(sacc[mt][nt][2], SCL, amv[nt][0]));
                    float p3 = ex2(fmaf(sacc[mt][nt][3], SCL, amv[nt][1]));
                    lrow[mt][0] += p0 + p1;
                    lrow[mt][1] += p2 + p3;
                    sacc[mt][nt][0] = p0;   // fp32 bits; HMMA truncates to tf32
                    sacc[mt][nt][1] = p1;
                    sacc[mt][nt][2] = p2;
                    sacc[mt][nt][3] = p3;
                }
            }
        }

        CPA_WAIT1();                       // V(t)'s group (older) retired
        __syncthreads();

        // ---- O += P V ; A-frags via intra-quad shuffles ----
#pragma unroll
        for (int kk = 0; kk < 4; ++kk) {
            uint32_t af[2][4];
#pragma unroll
            for (int mt = 0; mt < 2; ++mt) {
                uint32_t p0 = __float_as_uint(sacc[mt][kk][0]);
                uint32_t p1 = __float_as_uint(sacc[mt][kk][1]);
                uint32_t p2 = __float_as_uint(sacc[mt][kk][2]);
                uint32_t p3 = __float_as_uint(sacc[mt][kk][3]);
                uint32_t x0 = __shfl_sync(0xffffffffu, p0, srcA);
                uint32_t x1 = __shfl_sync(0xffffffffu, p1, srcA);
                uint32_t y0 = __shfl_sync(0xffffffffu, p0, srcB);
                uint32_t y1 = __shfl_sync(0xffffffffu, p1, srcB);
                af[mt][0] = (c & 1) ? x1 : x0;
                af[mt][2] = (c & 1) ? y1 : y0;
                uint32_t x2 = __shfl_sync(0xffffffffu, p2, srcA);
                uint32_t x3 = __shfl_sync(0xffffffffu, p3, srcA);
                uint32_t y2 = __shfl_sync(0xffffffffu, p2, srcB);
                uint32_t y3 = __shfl_sync(0xffffffffu, p3, srcB);
                af[mt][1] = (c & 1) ? x3 : x2;
                af[mt][3] = (c & 1) ? y3 : y2;
            }
#pragma unroll
            for (int nt = 0; nt < 8; ++nt) {
                uint32_t b0 = sm[SM_V + (kk * 8 + c) * VP + nt * 8 + g];
                uint32_t b1 = sm[SM_V + (kk * 8 + c + 4) * VP + nt * 8 + g];
#pragma unroll
                for (int mt = 0; mt < 2; ++mt)
                    mma_tf32(oacc[mt][nt][0], oacc[mt][nt][1], oacc[mt][nt][2], oacc[mt][nt][3],
                             af[mt][0], af[mt][1], af[mt][2], af[mt][3], b0, b1);
            }
        }

        __syncthreads();                   // V readers done
        if (t + 1 < NT_KV) issueV((t + 1) * 32);
        CPA_COMMIT();                      // group = V(t+1)
        CPA_WAIT1();                       // K(t+1) retired; V(t+1) may fly
        __syncthreads();
    }

    // ---- epilogue: quad-reduce l, normalize, write ----
#pragma unroll
    for (int mt = 0; mt < 2; ++mt) {
#pragma unroll
        for (int off = 1; off <= 2; off <<= 1) {
            lrow[mt][0] += __shfl_xor_sync(0xffffffffu, lrow[mt][0], off);
            lrow[mt][1] += __shfl_xor_sync(0xffffffffu, lrow[mt][1], off);
        }
        float inv_lo = 1.0f / lrow[mt][0];
        float inv_hi = 1.0f / lrow[mt][1];
        int row_lo = r0 + wid * 32 + mt * 16 + g;
#pragma unroll
        for (int nt = 0; nt < 8; ++nt) {
            int col = head * WHEAD + nt * 8 + 2 * c;
            float2 lo = make_float2(oacc[mt][nt][0] * inv_lo, oacc[mt][nt][1] * inv_lo);
            float2 hi = make_float2(oacc[mt][nt][2] * inv_hi, oacc[mt][nt][3] * inv_hi);
            *(float2*)&out[(size_t)row_lo * D_MODEL + col] = lo;
            *(float2*)&out[(size_t)(row_lo + 8) * D_MODEL + col] = hi;
        }
    }
}

// ---------------- launch ----------------
extern "C" void kernel_launch(void* const* d_in, const int* in_sizes, int n_in,
                              void* d_out, int out_size)
{
    const float* x    = (const float*)d_in[0];
    const float* mask = (const float*)d_in[1];
    const float* Wq   = (const float*)d_in[2];
    const float* bq   = (const float*)d_in[3];
    float* out = (float*)d_out;

    dim3 gGemm(N_QKV / 64, S_LEN / 128);         // (36, 32)
    qkv_gemm_tc<<<gGemm, 256>>>(x, Wq, bq);

    cudaFuncSetAttribute(attn_tc,
                         cudaFuncAttributeMaxDynamicSharedMemorySize,
                         ATTN_SMEM_BYTES);
    dim3 gAttn(S_LEN / 128, NHEAD);              // (32, 12)
    attn_tc<<<gAttn, 128, ATTN_SMEM_BYTES>>>(mask, out);
}

// round 11
// speedup vs baseline: 1.8876x; 1.0540x over previous
#include <cuda_runtime.h>
#include <cuda_bf16.h>
#include <cstdint>

#define S_LEN 4096
#define D_MODEL 768
#define NHEAD 12
#define WHEAD 64
#define N_QKV 2304
#define NSPLIT 4
#define NT_KV (S_LEN / 32)          // 128 kv tiles total
#define NT_PER (NT_KV / NSPLIT)     // 32 per split

// ---------------- scratch ----------------
__device__ float g_q[NHEAD * S_LEN * WHEAD];    // tf32 bits [h][s][w]
__device__ float g_kt[NHEAD * WHEAD * S_LEN];   // tf32 bits [h][w][s]
__device__ float g_v[NHEAD * S_LEN * WHEAD];    // tf32 bits [h][s][w]
__device__ float g_os[NSPLIT * NHEAD * S_LEN * WHEAD];  // unnormalized O partials
__device__ float g_ls[NSPLIT * NHEAD * S_LEN];          // l partials

// ---------------- helpers ----------------
__device__ __forceinline__ uint32_t f2tf32(float x) {
    uint32_t u;
    asm("cvt.rna.tf32.f32 %0, %1;" : "=r"(u) : "f"(x));
    return u;
}
__device__ __forceinline__ float ex2(float x) {
    float y;
    asm("ex2.approx.f32 %0, %1;" : "=f"(y) : "f"(x));
    return y;
}

__device__ __forceinline__ void mma_tf32(
    float& d0, float& d1, float& d2, float& d3,
    uint32_t a0, uint32_t a1, uint32_t a2, uint32_t a3,
    uint32_t b0, uint32_t b1)
{
    asm volatile(
        "mma.sync.aligned.m16n8k8.row.col.f32.tf32.tf32.f32 "
        "{%0,%1,%2,%3},{%4,%5,%6,%7},{%8,%9},{%0,%1,%2,%3};"
        : "+f"(d0), "+f"(d1), "+f"(d2), "+f"(d3)
        : "r"(a0), "r"(a1), "r"(a2), "r"(a3), "r"(b0), "r"(b1));
}

__device__ __forceinline__ void cpa16(void* s, const void* g) {
    uint32_t sa = (uint32_t)__cvta_generic_to_shared(s);
    asm volatile("cp.async.cg.shared.global [%0], [%1], 16;" :: "r"(sa), "l"(g));
}
#define CPA_COMMIT() asm volatile("cp.async.commit_group;" ::: "memory")
#define CPA_WAIT0()  asm volatile("cp.async.wait_group 0;" ::: "memory")
#define CPA_WAIT1()  asm volatile("cp.async.wait_group 1;" ::: "memory")

// =============== Kernel 1: QKV GEMM (tf32, cp.async double-buffered) ===============
#define GAP 36
#define GBP 72

__global__ __launch_bounds__(256) void qkv_gemm_tc(
    const float* __restrict__ X, const float* __restrict__ Wq,
    const float* __restrict__ bq)
{
    __shared__ float As[2][128 * GAP];
    __shared__ float Bs[2][32 * GBP];

    const int tid = threadIdx.x;
    const int wid = tid >> 5;
    const int lane = tid & 31;
    const int g = lane >> 2;
    const int c = lane & 3;
    const int warp_m = wid >> 1;
    const int warp_n = wid & 1;
    const int m0 = blockIdx.y * 128;
    const int n0 = blockIdx.x * 64;

    float acc[2][4][4];
#pragma unroll
    for (int mt = 0; mt < 2; ++mt)
#pragma unroll
        for (int nt = 0; nt < 4; ++nt)
#pragma unroll
            for (int i = 0; i < 4; ++i) acc[mt][nt][i] = 0.0f;

    const int rowA = tid >> 3, c4A = tid & 7;
    const int rowB = tid >> 4, c4B = tid & 15;

    auto issue = [&](int k0, int buf) {
#pragma unroll
        for (int r = 0; r < 4; ++r) {
            int row = rowA + r * 32;
            cpa16(&As[buf][row * GAP + c4A * 4],
                  &X[(size_t)(m0 + row) * D_MODEL + k0 + c4A * 4]);
        }
#pragma unroll
        for (int r = 0; r < 2; ++r) {
            int row = rowB + r * 16;
            cpa16(&Bs[buf][row * GBP + c4B * 4],
                  &Wq[(size_t)(k0 + row) * N_QKV + n0 + c4B * 4]);
        }
        CPA_COMMIT();
    };

    issue(0, 0);
    for (int i = 0; i < 24; ++i) {
        CPA_WAIT0();
        __syncthreads();
        if (i + 1 < 24) issue((i + 1) * 32, (i + 1) & 1);
        const float* A = As[i & 1];
        const float* B = Bs[i & 1];
#pragma unroll
        for (int kk = 0; kk < 4; ++kk) {
            uint32_t af[2][4];
#pragma unroll
            for (int mt = 0; mt < 2; ++mt) {
                int mr = warp_m * 32 + mt * 16 + g;
                af[mt][0] = f2tf32(A[mr * GAP + kk * 8 + c]);
                af[mt][1] = f2tf32(A[(mr + 8) * GAP + kk * 8 + c]);
                af[mt][2] = f2tf32(A[mr * GAP + kk * 8 + c + 4]);
                af[mt][3] = f2tf32(A[(mr + 8) * GAP + kk * 8 + c + 4]);
            }
#pragma unroll
            for (int nt = 0; nt < 4; ++nt) {
                int nc = warp_n * 32 + nt * 8 + g;
                uint32_t b0 = f2tf32(B[(kk * 8 + c) * GBP + nc]);
                uint32_t b1 = f2tf32(B[(kk * 8 + c + 4) * GBP + nc]);
#pragma unroll
                for (int mt = 0; mt < 2; ++mt)
                    mma_tf32(acc[mt][nt][0], acc[mt][nt][1], acc[mt][nt][2], acc[mt][nt][3],
                             af[mt][0], af[mt][1], af[mt][2], af[mt][3], b0, b1);
            }
        }
        __syncthreads();
    }

    const int sel = n0 / D_MODEL;
    const int head = (n0 % D_MODEL) / WHEAD;

#pragma unroll
    for (int mt = 0; mt < 2; ++mt) {
#pragma unroll
        for (int nt = 0; nt < 4; ++nt) {
            int w = warp_n * 32 + nt * 8 + 2 * c;
            float b0 = bq[n0 + w], b1 = bq[n0 + w + 1];
            int m_lo = m0 + warp_m * 32 + mt * 16 + g;
            float v00 = __uint_as_float(f2tf32(acc[mt][nt][0] + b0));
            float v01 = __uint_as_float(f2tf32(acc[mt][nt][1] + b1));
            float v10 = __uint_as_float(f2tf32(acc[mt][nt][2] + b0));
            float v11 = __uint_as_float(f2tf32(acc[mt][nt][3] + b1));
            if (sel == 1) {   // K: [h][w][s]
                float* kt = g_kt + (size_t)head * WHEAD * S_LEN;
                kt[(size_t)w * S_LEN + m_lo] = v00;
                kt[(size_t)(w + 1) * S_LEN + m_lo] = v01;
                kt[(size_t)w * S_LEN + m_lo + 8] = v10;
                kt[(size_t)(w + 1) * S_LEN + m_lo + 8] = v11;
            } else {
                float* dst = (sel == 0) ? g_q : g_v;
                *(float2*)&dst[((size_t)head * S_LEN + m_lo) * WHEAD + w] = make_float2(v00, v01);
                *(float2*)&dst[((size_t)head * S_LEN + m_lo + 8) * WHEAD + w] = make_float2(v10, v11);
            }
        }
    }
}

// =============== Kernel 2: flash attention (BC=32, split-KV x4) ===============
#define QPITCH 68
#define KP     40
#define VP     72
#define SM_Q   0
#define SM_K   (128 * QPITCH)
#define SM_V   (SM_K + 64 * KP)
#define SM_AM  (SM_V + 32 * VP)
#define ATTN_SMEM_F (SM_AM + 2 * 32)
#define ATTN_SMEM_BYTES (ATTN_SMEM_F * 4)   // 54528 B -> 4 CTAs/SM

#define LOG2E 1.4426950408889634f
#define SCL   (0.125f * LOG2E)
#define AMC   (10000.0f * LOG2E)

__global__ __launch_bounds__(128, 4) void attn_tc(
    const float* __restrict__ mask)
{
    extern __shared__ uint32_t sm[];
    float* smf = (float*)sm;

    const int tid = threadIdx.x;
    const int wid = tid >> 5;
    const int lane = tid & 31;
    const int g = lane >> 2;
    const int c = lane & 3;
    const int srcA = (lane & 28) | (c >> 1);
    const int srcB = srcA + 2;
    const int r0 = blockIdx.x * 128;
    const int head = blockIdx.y;
    const int split = blockIdx.z;
    const int tb = split * NT_PER;      // first kv tile of this split

    const float* qh = g_q + (size_t)head * S_LEN * WHEAD;
    const float* kt = g_kt + (size_t)head * WHEAD * S_LEN;
    const float* vh = g_v + (size_t)head * S_LEN * WHEAD;

    const int qRow = tid >> 4, qC4 = tid & 15;
    const int kRow = tid >> 3, kC4 = tid & 7;

    auto issueK = [&](int t0) {
#pragma unroll
        for (int r = 0; r < 4; ++r) {
            int w = kRow + r * 16;
            cpa16(&sm[SM_K + w * KP + kC4 * 4], &kt[(size_t)w * S_LEN + t0 + kC4 * 4]);
        }
        if (tid < 8) cpa16(&sm[SM_AM + ((t0 >> 5) & 1) * 32 + tid * 4], &mask[t0 + tid * 4]);
    };
    auto issueV = [&](int t0) {
#pragma unroll
        for (int r = 0; r < 4; ++r) {
            int j = qRow + r * 8;
            cpa16(&sm[SM_V + j * VP + qC4 * 4], &vh[(size_t)(t0 + j) * WHEAD + qC4 * 4]);
        }
    };

    // ---- prologue: Q (128x64), K(first), V(first), mask — one group ----
#pragma unroll
    for (int r = 0; r < 16; ++r) {
        int row = qRow + r * 8;
        cpa16(&sm[SM_Q + row * QPITCH + qC4 * 4],
              &qh[(size_t)(r0 + row) * WHEAD + qC4 * 4]);
    }
    issueK(tb * 32);
    issueV(tb * 32);
    CPA_COMMIT();

    float oacc[2][8][4];
#pragma unroll
    for (int mt = 0; mt < 2; ++mt)
#pragma unroll
        for (int nt = 0; nt < 8; ++nt)
#pragma unroll
            for (int i = 0; i < 4; ++i) oacc[mt][nt][i] = 0.0f;
    float lrow[2][2];
    lrow[0][0] = lrow[0][1] = lrow[1][0] = lrow[1][1] = 0.0f;

    CPA_WAIT0();
    __syncthreads();

    for (int tt = 0; tt < NT_PER; ++tt) {
        const int t = tb + tt;
        // ---- S = Q K^T : 32 rows x 32 kv-cols per warp ----
        float sacc[2][4][4];
#pragma unroll
        for (int mt = 0; mt < 2; ++mt)
#pragma unroll
            for (int nt = 0; nt < 4; ++nt)
#pragma unroll
                for (int i = 0; i < 4; ++i) sacc[mt][nt][i] = 0.0f;

#pragma unroll
        for (int kk = 0; kk < 8; ++kk) {
            uint32_t af[2][4];
#pragma unroll
            for (int mt = 0; mt < 2; ++mt) {
                int mr = wid * 32 + mt * 16 + g;
                af[mt][0] = sm[SM_Q + mr * QPITCH + kk * 8 + c];
                af[mt][1] = sm[SM_Q + (mr + 8) * QPITCH + kk * 8 + c];
                af[mt][2] = sm[SM_Q + mr * QPITCH + kk * 8 + c + 4];
                af[mt][3] = sm[SM_Q + (mr + 8) * QPITCH + kk * 8 + c + 4];
            }
#pragma unroll
            for (int nt = 0; nt < 4; ++nt) {
                uint32_t b0 = sm[SM_K + (kk * 8 + c) * KP + nt * 8 + g];
                uint32_t b1 = sm[SM_K + (kk * 8 + c + 4) * KP + nt * 8 + g];
#pragma unroll
                for (int mt = 0; mt < 2; ++mt)
                    mma_tf32(sacc[mt][nt][0], sacc[mt][nt][1], sacc[mt][nt][2], sacc[mt][nt][3],
                             af[mt][0], af[mt][1], af[mt][2], af[mt][3], b0, b1);
            }
        }

        __syncthreads();                   // K readers done
        if (tt + 1 < NT_PER) issueK((t + 1) * 32);
        CPA_COMMIT();                      // group = K(t+1)+mask(t+1)

        // ---- static-max softmax ----
        {
            float amv[4][2];
#pragma unroll
            for (int nt = 0; nt < 4; ++nt) {
                float m0v = smf[SM_AM + (t & 1) * 32 + nt * 8 + 2 * c];
                float m1v = smf[SM_AM + (t & 1) * 32 + nt * 8 + 2 * c + 1];
                amv[nt][0] = fmaf(m0v, AMC, -AMC);
                amv[nt][1] = fmaf(m1v, AMC, -AMC);
            }
#pragma unroll
            for (int mt = 0; mt < 2; ++mt) {
#pragma unroll
                for (int nt = 0; nt < 4; ++nt) {
                    float p0 = ex2(fmaf(sacc[mt][nt][0], SCL, amv[nt][0]));
                    float p1 = ex2(fmaf(sacc[mt][nt][1], SCL, amv[nt][1]));
                    float p2 = ex2(fmaf(sacc[mt][nt][2], SCL, amv[nt][0]));
                    float p3 = ex2(fmaf(sacc[mt][nt][3], SCL, amv[nt][1]));
                    lrow[mt][0] += p0 + p1;
                    lrow[mt][1] += p2 + p3;
                    sacc[mt][nt][0] = p0;
                    sacc[mt][nt][1] = p1;
                    sacc[mt][nt][2] = p2;
                    sacc[mt][nt][3] = p3;
                }
            }
        }

        CPA_WAIT1();                       // V(t)'s group (older) retired
        __syncthreads();

        // ---- O += P V ----
#pragma unroll
        for (int kk = 0; kk < 4; ++kk) {
            uint32_t af[2][4];
#pragma unroll
            for (int mt = 0; mt < 2; ++mt) {
                uint32_t p0 = __float_as_uint(sacc[mt][kk][0]);
                uint32_t p1 = __float_as_uint(sacc[mt][kk][1]);
                uint32_t p2 = __float_as_uint(sacc[mt][kk][2]);
                uint32_t p3 = __float_as_uint(sacc[mt][kk][3]);
                uint32_t x0 = __shfl_sync(0xffffffffu, p0, srcA);
                uint32_t x1 = __shfl_sync(0xffffffffu, p1, srcA);
                uint32_t y0 = __shfl_sync(0xffffffffu, p0, srcB);
                uint32_t y1 = __shfl_sync(0xffffffffu, p1, srcB);
                af[mt][0] = (c & 1) ? x1 : x0;
                af[mt][2] = (c & 1) ? y1 : y0;
                uint32_t x2 = __shfl_sync(0xffffffffu, p2, srcA);
                uint32_t x3 = __shfl_sync(0xffffffffu, p3, srcA);
                uint32_t y2 = __shfl_sync(0xffffffffu, p2, srcB);
                uint32_t y3 = __shfl_sync(0xffffffffu, p3, srcB);
                af[mt][1] = (c & 1) ? x3 : x2;
                af[mt][3] = (c & 1) ? y3 : y2;
            }
#pragma unroll
            for (int nt = 0; nt < 8; ++nt) {
                uint32_t b0 = sm[SM_V + (kk * 8 + c) * VP + nt * 8 + g];
                uint32_t b1 = sm[SM_V + (kk * 8 + c + 4) * VP + nt * 8 + g];
#pragma unroll
                for (int mt = 0; mt < 2; ++mt)
                    mma_tf32(oacc[mt][nt][0], oacc[mt][nt][1], oacc[mt][nt][2], oacc[mt][nt][3],
                             af[mt][0], af[mt][1], af[mt][2], af[mt][3], b0, b1);
            }
        }

        __syncthreads();                   // V readers done
        if (tt + 1 < NT_PER) issueV((t + 1) * 32);
        CPA_COMMIT();                      // group = V(t+1)
        CPA_WAIT1();                       // K(t+1) retired
        __syncthreads();
    }

    // ---- epilogue: quad-reduce l, write unnormalized partials ----
    float* op = g_os + ((size_t)(split * NHEAD + head) * S_LEN) * WHEAD;
    float* lp = g_ls + (size_t)(split * NHEAD + head) * S_LEN;
#pragma unroll
    for (int mt = 0; mt < 2; ++mt) {
#pragma unroll
        for (int off = 1; off <= 2; off <<= 1) {
            lrow[mt][0] += __shfl_xor_sync(0xffffffffu, lrow[mt][0], off);
            lrow[mt][1] += __shfl_xor_sync(0xffffffffu, lrow[mt][1], off);
        }
        int row_lo = r0 + wid * 32 + mt * 16 + g;
        if (c == 0) {
            lp[row_lo] = lrow[mt][0];
            lp[row_lo + 8] = lrow[mt][1];
        }
#pragma unroll
        for (int nt = 0; nt < 8; ++nt) {
            int col = nt * 8 + 2 * c;
            *(float2*)&op[(size_t)row_lo * WHEAD + col] =
                make_float2(oacc[mt][nt][0], oacc[mt][nt][1]);
            *(float2*)&op[(size_t)(row_lo + 8) * WHEAD + col] =
                make_float2(oacc[mt][nt][2], oacc[mt][nt][3]);
        }
    }
}

// =============== Kernel 3: combine splits ===============
// out[s][h*64+w] = sum_p O[p][h][s][w] / sum_p l[p][h][s]
__global__ __launch_bounds__(256) void combine_k(float* __restrict__ out)
{
    int idx = blockIdx.x * 256 + threadIdx.x;     // 0 .. 4096*12*16-1 (per float4)
    int w4 = idx & 15;
    int hs = idx >> 4;        // 0 .. 4096*12-1
    int h = hs % NHEAD;
    int s = hs / NHEAD;

    float4 o = make_float4(0.f, 0.f, 0.f, 0.f);
    float l = 0.f;
#pragma unroll
    for (int p = 0; p < NSPLIT; ++p) {
        const float* op = g_os + (((size_t)(p * NHEAD + h) * S_LEN + s) * WHEAD);
        float4 v = *(const float4*)&op[w4 * 4];
        o.x += v.x; o.y += v.y; o.z += v.z; o.w += v.w;
        l += g_ls[(size_t)(p * NHEAD + h) * S_LEN + s];
    }
    float inv = 1.0f / l;
    o.x *= inv; o.y *= inv; o.z *= inv; o.w *= inv;
    *(float4*)&out[(size_t)s * D_MODEL + h * WHEAD + w4 * 4] = o;
}

// ---------------- launch ----------------
extern "C" void kernel_launch(void* const* d_in, const int* in_sizes, int n_in,
                              void* d_out, int out_size)
{
    const float* x    = (const float*)d_in[0];
    const float* mask = (const float*)d_in[1];
    const float* Wq   = (const float*)d_in[2];
    const float* bq   = (const float*)d_in[3];
    float* out = (float*)d_out;

    dim3 gGemm(N_QKV / 64, S_LEN / 128);         // (36, 32)
    qkv_gemm_tc<<<gGemm, 256>>>(x, Wq, bq);

    cudaFuncSetAttribute(attn_tc,
                         cudaFuncAttributeMaxDynamicSharedMemorySize,
                         ATTN_SMEM_BYTES);
    dim3 gAttn(S_LEN / 128, NHEAD, NSPLIT);      // (32, 12, 4) = 1536 CTAs
    attn_tc<<<gAttn, 128, ATTN_SMEM_BYTES>>>(mask);

    combine_k<<<(S_LEN * NHEAD * 16) / 256, 256>>>(out);   // 3072 blocks
}

// round 14
// speedup vs baseline: 2.8490x; 1.5093x over previous
#include <cuda_runtime.h>
#include <cuda_fp16.h>
#include <cstdint>

#define S_LEN 4096
#define D_MODEL 768
#define NHEAD 12
#define WHEAD 64
#define N_QKV 2304
#define NSPLIT 4
#define NT_KV (S_LEN / 32)
#define NT_PER (NT_KV / NSPLIT)

// ---------------- scratch ----------------
__device__ __half g_q[NHEAD * S_LEN * WHEAD];   // [h][s][w] fp16
__device__ __half g_k[NHEAD * S_LEN * WHEAD];   // [h][s][w] fp16
__device__ __half g_vt[NHEAD * WHEAD * S_LEN];  // [h][w][s] fp16 (transposed)
__device__ float g_os[NSPLIT * NHEAD * S_LEN * WHEAD];
__device__ float g_ls[NSPLIT * NHEAD * S_LEN];

// ---------------- helpers ----------------
__device__ __forceinline__ uint32_t f2tf32(float x) {
    uint32_t u;
    asm("cvt.rna.tf32.f32 %0, %1;" : "=r"(u) : "f"(x));
    return u;
}
__device__ __forceinline__ float ex2(float x) {
    float y;
    asm("ex2.approx.f32 %0, %1;" : "=f"(y) : "f"(x));
    return y;
}
// pack (lo,hi) floats -> f16x2 (lo in bits[15:0])
__device__ __forceinline__ uint32_t pack2(float lo, float hi) {
    uint32_t r;
    asm("cvt.rn.f16x2.f32 %0, %1, %2;" : "=r"(r) : "f"(hi), "f"(lo));
    return r;
}

__device__ __forceinline__ void mma_tf32(
    float& d0, float& d1, float& d2, float& d3,
    uint32_t a0, uint32_t a1, uint32_t a2, uint32_t a3,
    uint32_t b0, uint32_t b1)
{
    asm volatile(
        "mma.sync.aligned.m16n8k8.row.col.f32.tf32.tf32.f32 "
        "{%0,%1,%2,%3},{%4,%5,%6,%7},{%8,%9},{%0,%1,%2,%3};"
        : "+f"(d0), "+f"(d1), "+f"(d2), "+f"(d3)
        : "r"(a0), "r"(a1), "r"(a2), "r"(a3), "r"(b0), "r"(b1));
}

__device__ __forceinline__ void mma_f16(
    float& d0, float& d1, float& d2, float& d3,
    uint32_t a0, uint32_t a1, uint32_t a2, uint32_t a3,
    uint32_t b0, uint32_t b1)
{
    asm volatile(
        "mma.sync.aligned.m16n8k16.row.col.f32.f16.f16.f32 "
        "{%0,%1,%2,%3},{%4,%5,%6,%7},{%8,%9},{%0,%1,%2,%3};"
        : "+f"(d0), "+f"(d1), "+f"(d2), "+f"(d3)
        : "r"(a0), "r"(a1), "r"(a2), "r"(a3), "r"(b0), "r"(b1));
}

__device__ __forceinline__ void cpa16(void* s, const void* g) {
    uint32_t sa = (uint32_t)__cvta_generic_to_shared(s);
    asm volatile("cp.async.cg.shared.global [%0], [%1], 16;" :: "r"(sa), "l"(g));
}
#define CPA_COMMIT() asm volatile("cp.async.commit_group;" ::: "memory")
#define CPA_WAIT0()  asm volatile("cp.async.wait_group 0;" ::: "memory")
#define CPA_WAIT1()  asm volatile("cp.async.wait_group 1;" ::: "memory")

// =============== Kernel 1: QKV GEMM (tf32 compute, fp16 outputs) ===============
#define GAP 36
#define GBP 72

__global__ __launch_bounds__(256) void qkv_gemm_tc(
    const float* __restrict__ X, const float* __restrict__ Wq,
    const float* __restrict__ bq)
{
    __shared__ float As[2][128 * GAP];
    __shared__ float Bs[2][32 * GBP];

    const int tid = threadIdx.x;
    const int wid = tid >> 5;
    const int lane = tid & 31;
    const int g = lane >> 2;
    const int c = lane & 3;
    const int warp_m = wid >> 1;
    const int warp_n = wid & 1;
    const int m0 = blockIdx.y * 128;
    const int n0 = blockIdx.x * 64;

    float acc[2][4][4];
#pragma unroll
    for (int mt = 0; mt < 2; ++mt)
#pragma unroll
        for (int nt = 0; nt < 4; ++nt)
#pragma unroll
            for (int i = 0; i < 4; ++i) acc[mt][nt][i] = 0.0f;

    const int rowA = tid >> 3, c4A = tid & 7;
    const int rowB = tid >> 4, c4B = tid & 15;

    auto issue = [&](int k0, int buf) {
#pragma unroll
        for (int r = 0; r < 4; ++r) {
            int row = rowA + r * 32;
            cpa16(&As[buf][row * GAP + c4A * 4],
                  &X[(size_t)(m0 + row) * D_MODEL + k0 + c4A * 4]);
        }
#pragma unroll
        for (int r = 0; r < 2; ++r) {
            int row = rowB + r * 16;
            cpa16(&Bs[buf][row * GBP + c4B * 4],
                  &Wq[(size_t)(k0 + row) * N_QKV + n0 + c4B * 4]);
        }
        CPA_COMMIT();
    };

    issue(0, 0);
    for (int i = 0; i < 24; ++i) {
        CPA_WAIT0();
        __syncthreads();
        if (i + 1 < 24) issue((i + 1) * 32, (i + 1) & 1);
        const float* A = As[i & 1];
        const float* B = Bs[i & 1];
#pragma unroll
        for (int kk = 0; kk < 4; ++kk) {
            uint32_t af[2][4];
#pragma unroll
            for (int mt = 0; mt < 2; ++mt) {
                int mr = warp_m * 32 + mt * 16 + g;
                af[mt][0] = f2tf32(A[mr * GAP + kk * 8 + c]);
                af[mt][1] = f2tf32(A[(mr + 8) * GAP + kk * 8 + c]);
                af[mt][2] = f2tf32(A[mr * GAP + kk * 8 + c + 4]);
                af[mt][3] = f2tf32(A[(mr + 8) * GAP + kk * 8 + c + 4]);
            }
#pragma unroll
            for (int nt = 0; nt < 4; ++nt) {
                int nc = warp_n * 32 + nt * 8 + g;
                uint32_t b0 = f2tf32(B[(kk * 8 + c) * GBP + nc]);
                uint32_t b1 = f2tf32(B[(kk * 8 + c + 4) * GBP + nc]);
#pragma unroll
                for (int mt = 0; mt < 2; ++mt)
                    mma_tf32(acc[mt][nt][0], acc[mt][nt][1], acc[mt][nt][2], acc[mt][nt][3],
                             af[mt][0], af[mt][1], af[mt][2], af[mt][3], b0, b1);
            }
        }
        __syncthreads();
    }

    const int sel = n0 / D_MODEL;
    const int head = (n0 % D_MODEL) / WHEAD;

#pragma unroll
    for (int mt = 0; mt < 2; ++mt) {
#pragma unroll
        for (int nt = 0; nt < 4; ++nt) {
            int w = warp_n * 32 + nt * 8 + 2 * c;
            float b0 = bq[n0 + w], b1 = bq[n0 + w + 1];
            int m_lo = m0 + warp_m * 32 + mt * 16 + g;
            float v00 = acc[mt][nt][0] + b0;
            float v01 = acc[mt][nt][1] + b1;
            float v10 = acc[mt][nt][2] + b0;
            float v11 = acc[mt][nt][3] + b1;
            if (sel == 2) {   // V transposed: [h][w][s]
                __half* vt = g_vt + (size_t)head * WHEAD * S_LEN;
                vt[(size_t)w * S_LEN + m_lo] = __float2half_rn(v00);
                vt[(size_t)(w + 1) * S_LEN + m_lo] = __float2half_rn(v01);
                vt[(size_t)w * S_LEN + m_lo + 8] = __float2half_rn(v10);
                vt[(size_t)(w + 1) * S_LEN + m_lo + 8] = __float2half_rn(v11);
            } else {          // Q/K natural: [h][s][w]
                __half* dst = (sel == 0) ? g_q : g_k;
                *(__half2*)&dst[((size_t)head * S_LEN + m_lo) * WHEAD + w] =
                    __floats2half2_rn(v00, v01);
                *(__half2*)&dst[((size_t)head * S_LEN + m_lo + 8) * WHEAD + w] =
                    __floats2half2_rn(v10, v11);
            }
        }
    }
}

// =============== Kernel 2: flash attention (fp16 MMA, BC=32, split-KV x4) ===============
#define QP  72    // 144 B row stride; word-stride 36 == 4 (mod 32)
#define KPH 72
#define VPH 40    // 80 B row stride; word-stride 20 -> all phases distinct
#define SM_Q   0
#define SM_K   (128 * QP)              // 9216
#define SM_V   (SM_K + 32 * KPH)       // 11520
#define SM_END (SM_V + 64 * VPH)       // 14080 halves
#define SM_AM_F (SM_END / 2)           // float index of mask area
#define ATTN_SMEM_BYTES (SM_END * 2 + 2 * 32 * 4)   // 28416 B

#define LOG2E 1.4426950408889634f
#define SCL   (0.125f * LOG2E)
#define AMC   (10000.0f * LOG2E)

__global__ __launch_bounds__(128, 4) void attn_tc(
    const float* __restrict__ mask)
{
    extern __shared__ __half smh[];
    float* smf = (float*)smh;

    const int tid = threadIdx.x;
    const int wid = tid >> 5;
    const int lane = tid & 31;
    const int g = lane >> 2;
    const int c = lane & 3;
    const int r0 = blockIdx.x * 128;
    const int head = blockIdx.y;
    const int split = blockIdx.z;
    const int tb = split * NT_PER;

    const __half* qh = g_q + (size_t)head * S_LEN * WHEAD;
    const __half* kh = g_k + (size_t)head * S_LEN * WHEAD;
    const __half* vt = g_vt + (size_t)head * WHEAD * S_LEN;

    const int r8 = tid >> 3, c8 = tid & 7;
    const int r4 = tid >> 2, c4 = tid & 3;

    auto issueK = [&](int t0) {
#pragma unroll
        for (int r = 0; r < 2; ++r) {
            int row = r8 + r * 16;
            cpa16(&smh[SM_K + row * KPH + c8 * 8],
                  &kh[(size_t)(t0 + row) * WHEAD + c8 * 8]);
        }
        if (tid < 8) cpa16(&smf[SM_AM_F + ((t0 >> 5) & 1) * 32 + tid * 4], &mask[t0 + tid * 4]);
    };
    auto issueV = [&](int t0) {
#pragma unroll
        for (int r = 0; r < 2; ++r) {
            int w = r4 + r * 32;
            cpa16(&smh[SM_V + w * VPH + c4 * 8],
                  &vt[(size_t)w * S_LEN + t0 + c4 * 8]);
        }
    };

    // ---- prologue ----
#pragma unroll
    for (int r = 0; r < 8; ++r) {
        int row = r8 + r * 16;
        cpa16(&smh[SM_Q + row * QP + c8 * 8],
              &qh[(size_t)(r0 + row) * WHEAD + c8 * 8]);
    }
    issueK(tb * 32);
    issueV(tb * 32);
    CPA_COMMIT();

    float oacc[2][8][4];
#pragma unroll
    for (int mt = 0; mt < 2; ++mt)
#pragma unroll
        for (int nt = 0; nt < 8; ++nt)
#pragma unroll
            for (int i = 0; i < 4; ++i) oacc[mt][nt][i] = 0.0f;
    float lrow[2][2];
    lrow[0][0] = lrow[0][1] = lrow[1][0] = lrow[1][1] = 0.0f;

    CPA_WAIT0();
    __syncthreads();

    for (int tt = 0; tt < NT_PER; ++tt) {
        const int t = tb + tt;

        // ---- S = Q K^T : fp16 m16n8k16, 4 k-steps ----
        float sacc[2][4][4];
#pragma unroll
        for (int mt = 0; mt < 2; ++mt)
#pragma unroll
            for (int nt = 0; nt < 4; ++nt)
#pragma unroll
                for (int i = 0; i < 4; ++i) sacc[mt][nt][i] = 0.0f;

#pragma unroll
        for (int kk = 0; kk < 4; ++kk) {
            uint32_t af[2][4];
#pragma unroll
            for (int mt = 0; mt < 2; ++mt) {
                int mr = wid * 32 + mt * 16 + g;
                af[mt][0] = *(const uint32_t*)&smh[SM_Q + mr * QP + kk * 16 + 2 * c];
                af[mt][1] = *(const uint32_t*)&smh[SM_Q + (mr + 8) * QP + kk * 16 + 2 * c];
                af[mt][2] = *(const uint32_t*)&smh[SM_Q + mr * QP + kk * 16 + 8 + 2 * c];
                af[mt][3] = *(const uint32_t*)&smh[SM_Q + (mr + 8) * QP + kk * 16 + 8 + 2 * c];
            }
#pragma unroll
            for (int nt = 0; nt < 4; ++nt) {
                int kr = nt * 8 + g;
                uint32_t b0 = *(const uint32_t*)&smh[SM_K + kr * KPH + kk * 16 + 2 * c];
                uint32_t b1 = *(const uint32_t*)&smh[SM_K + kr * KPH + kk * 16 + 8 + 2 * c];
#pragma unroll
                for (int mt = 0; mt < 2; ++mt)
                    mma_f16(sacc[mt][nt][0], sacc[mt][nt][1], sacc[mt][nt][2], sacc[mt][nt][3],
                            af[mt][0], af[mt][1], af[mt][2], af[mt][3], b0, b1);
            }
        }

        __syncthreads();                   // K readers done
        if (tt + 1 < NT_PER) issueK((t + 1) * 32);
        CPA_COMMIT();                      // group = K(t+1)+mask(t+1)

        // ---- static-max softmax ----
        {
            float amv[4][2];
#pragma unroll
            for (int nt = 0; nt < 4; ++nt) {
                float m0v = smf[SM_AM_F + (t & 1) * 32 + nt * 8 + 2 * c];
                float m1v = smf[SM_AM_F + (t & 1) * 32 + nt * 8 + 2 * c + 1];
                amv[nt][0] = fmaf(m0v, AMC, -AMC);
                amv[nt][1] = fmaf(m1v, AMC, -AMC);
            }
#pragma unroll
            for (int mt = 0; mt < 2; ++mt) {
#pragma unroll
                for (int nt = 0; nt < 4; ++nt) {
                    float p0 = ex2(fmaf(sacc[mt][nt][0], SCL, amv[nt][0]));
                    float p1 = ex2(fmaf(sacc[mt][nt][1], SCL, amv[nt][1]));
                    float p2 = ex2(fmaf(sacc[mt][nt][2], SCL, amv[nt][0]));
                    float p3 = ex2(fmaf(sacc[mt][nt][3], SCL, amv[nt][1]));
                    lrow[mt][0] += p0 + p1;
                    lrow[mt][1] += p2 + p3;
                    sacc[mt][nt][0] = p0;
                    sacc[mt][nt][1] = p1;
                    sacc[mt][nt][2] = p2;
                    sacc[mt][nt][3] = p3;
                }
            }
        }

        CPA_WAIT1();                       // V(t)'s group (older) retired
        __syncthreads();

        // ---- O += P V : fp16 m16n8k16, 2 k-steps; A-frags = packed C-frags ----
#pragma unroll
        for (int q = 0; q < 2; ++q) {
            uint32_t af[2][4];
#pragma unroll
            for (int mt = 0; mt < 2; ++mt) {
                af[mt][0] = pack2(sacc[mt][2 * q][0], sacc[mt][2 * q][1]);
                af[mt][1] = pack2(sacc[mt][2 * q][2], sacc[mt][2 * q][3]);
                af[mt][2] = pack2(sacc[mt][2 * q + 1][0], sacc[mt][2 * q + 1][1]);
                af[mt][3] = pack2(sacc[mt][2 * q + 1][2], sacc[mt][2 * q + 1][3]);
            }
#pragma unroll
            for (int nt = 0; nt < 8; ++nt) {
                int vr = nt * 8 + g;
                uint32_t b0 = *(const uint32_t*)&smh[SM_V + vr * VPH + q * 16 + 2 * c];
                uint32_t b1 = *(const uint32_t*)&smh[SM_V + vr * VPH + q * 16 + 8 + 2 * c];
#pragma unroll
                for (int mt = 0; mt < 2; ++mt)
                    mma_f16(oacc[mt][nt][0], oacc[mt][nt][1], oacc[mt][nt][2], oacc[mt][nt][3],
                            af[mt][0], af[mt][1], af[mt][2], af[mt][3], b0, b1);
            }
        }

        __syncthreads();                   // V readers done
        if (tt + 1 < NT_PER) issueV((t + 1) * 32);
        CPA_COMMIT();                      // group = V(t+1)
        CPA_WAIT1();                       // K(t+1) retired
        __syncthreads();
    }

    // ---- epilogue: quad-reduce l, write unnormalized partials ----
    float* op = g_os + ((size_t)(split * NHEAD + head) * S_LEN) * WHEAD;
    float* lp = g_ls + (size_t)(split * NHEAD + head) * S_LEN;
#pragma unroll
    for (int mt = 0; mt < 2; ++mt) {
#pragma unroll
        for (int off = 1; off <= 2; off <<= 1) {
            lrow[mt][0] += __shfl_xor_sync(0xffffffffu, lrow[mt][0], off);
            lrow[mt][1] += __shfl_xor_sync(0xffffffffu, lrow[mt][1], off);
        }
        int row_lo = r0 + wid * 32 + mt * 16 + g;
        if (c == 0) {
            lp[row_lo] = lrow[mt][0];
            lp[row_lo + 8] = lrow[mt][1];
        }
#pragma unroll
        for (int nt = 0; nt < 8; ++nt) {
            int col = nt * 8 + 2 * c;
            *(float2*)&op[(size_t)row_lo * WHEAD + col] =
                make_float2(oacc[mt][nt][0], oacc[mt][nt][1]);
            *(float2*)&op[(size_t)(row_lo + 8) * WHEAD + col] =
                make_float2(oacc[mt][nt][2], oacc[mt][nt][3]);
        }
    }
}

// =============== Kernel 3: combine splits ===============
__global__ __launch_bounds__(256) void combine_k(float* __restrict__ out)
{
    int idx = blockIdx.x * 256 + threadIdx.x;
    int w4 = idx & 15;
    int hs = idx >> 4;
    int h = hs % NHEAD;
    int s = hs / NHEAD;

    float4 o = make_float4(0.f, 0.f, 0.f, 0.f);
    float l = 0.f;
#pragma unroll
    for (int p = 0; p < NSPLIT; ++p) {
        const float* op = g_os + (((size_t)(p * NHEAD + h) * S_LEN + s) * WHEAD);
        float4 v = *(const float4*)&op[w4 * 4];
        o.x += v.x; o.y += v.y; o.z += v.z; o.w += v.w;
        l += g_ls[(size_t)(p * NHEAD + h) * S_LEN + s];
    }
    float inv = 1.0f / l;
    o.x *= inv; o.y *= inv; o.z *= inv; o.w *= inv;
    *(float4*)&out[(size_t)s * D_MODEL + h * WHEAD + w4 * 4] = o;
}

// ---------------- launch ----------------
extern "C" void kernel_launch(void* const* d_in, const int* in_sizes, int n_in,
                              void* d_out, int out_size)
{
    const float* x    = (const float*)d_in[0];
    const float* mask = (const float*)d_in[1];
    const float* Wq   = (const float*)d_in[2];
    const float* bq   = (const float*)d_in[3];
    float* out = (float*)d_out;

    dim3 gGemm(N_QKV / 64, S_LEN / 128);         // (36, 32)
    qkv_gemm_tc<<<gGemm, 256>>>(x, Wq, bq);

    cudaFuncSetAttribute(attn_tc,
                         cudaFuncAttributeMaxDynamicSharedMemorySize,
                         ATTN_SMEM_BYTES);
    dim3 gAttn(S_LEN / 128, NHEAD, NSPLIT);      // (32, 12, 4)
    attn_tc<<<gAttn, 128, ATTN_SMEM_BYTES>>>(mask);

    combine_k<<<(S_LEN * NHEAD * 16) / 256, 256>>>(out);
}